// round 6
// baseline (speedup 1.0000x reference)
#include <cuda_runtime.h>
#include <cuda_fp16.h>
#include <cstdint>
#include <cmath>

// ---------------------------------------------------------------------------
// GPT-OSS attention block on sm_100 (legacy mma.sync path).
// Round 6: deep pipeline GEMM — K-chunk 32, GS=4 stages (24KB each),
// 2 CTAs/SM, loads issued 3 chunks ahead; ldsm batched before each
// 32-MMA run. 2-pass hi/lo fp16 weights, fp16-hi activations.
// ---------------------------------------------------------------------------

#define T_LEN      1536
#define HIDDEN     2880
#define N_HEADS    64
#define N_KV       8
#define HEAD_DIM   64
#define WINDOW     128
#define Q_SIZE     4096
#define KV_SIZE    512
#define QKV_COLS   5120
#define O_NPAD     2944
#define ATT_SCALE  0.125f

// ---------------- scratch ---------------------------------------------------
__device__ __align__(256) float  g_qkv   [(size_t)T_LEN * QKV_COLS];
__device__ __align__(256) __half g_h_hi  [(size_t)T_LEN * HIDDEN];
__device__ __align__(256) __half g_wq_hi [(size_t)QKV_COLS * HIDDEN];   // [N,K]
__device__ __align__(256) __half g_wq_lo [(size_t)QKV_COLS * HIDDEN];
__device__ __align__(256) __half g_wo_hi [(size_t)O_NPAD * Q_SIZE];     // [N,K]
__device__ __align__(256) __half g_wo_lo [(size_t)O_NPAD * Q_SIZE];
__device__ __align__(256) __half g_a_hi  [(size_t)T_LEN * Q_SIZE];

// ---------------- helpers ---------------------------------------------------
static __device__ __forceinline__ uint32_t smem_u32(const void* p) {
    uint32_t a;
    asm("{ .reg .u64 t; cvta.to.shared.u64 t, %1; cvt.u32.u64 %0, t; }"
        : "=r"(a) : "l"(p));
    return a;
}

#define CP_ASYNC16(dst, src) \
    asm volatile("cp.async.cg.shared.global [%0], [%1], 16;" :: "r"(dst), "l"(src))
#define CP_COMMIT() asm volatile("cp.async.commit_group;")
#define CP_WAIT0()  asm volatile("cp.async.wait_group 0;")
#define CP_WAIT1()  asm volatile("cp.async.wait_group 1;")
#define CP_WAIT2()  asm volatile("cp.async.wait_group 2;")

static __device__ __forceinline__ void ldsm4(uint32_t* r, uint32_t addr) {
    asm volatile("ldmatrix.sync.aligned.m8n8.x4.shared.b16 {%0,%1,%2,%3}, [%4];"
                 : "=r"(r[0]), "=r"(r[1]), "=r"(r[2]), "=r"(r[3]) : "r"(addr));
}

static __device__ __forceinline__ void mma16816(float* d, const uint32_t* a,
                                                uint32_t b0, uint32_t b1) {
    asm volatile("mma.sync.aligned.m16n8k16.row.col.f32.f16.f16.f32 "
                 "{%0,%1,%2,%3}, {%4,%5,%6,%7}, {%8,%9}, {%0,%1,%2,%3};"
                 : "+f"(d[0]), "+f"(d[1]), "+f"(d[2]), "+f"(d[3])
                 : "r"(a[0]), "r"(a[1]), "r"(a[2]), "r"(a[3]), "r"(b0), "r"(b1));
}

// ---------------------------------------------------------------------------
// 2-pass fp16 HMMA GEMM:  C[M,Nreal] = A_hi[M,K] @ (B_hi+B_lo)[Npad,K]^T + bias
// CTA 128x128, K-chunk 32, stage = {Ahi 8K, Bhi 8K, Blo 8K}, GS=4 stages,
// 256 threads (8 warps of 64x32), 2 CTAs/SM. Rows are 64B -> SW64 swizzle.
// ---------------------------------------------------------------------------
#define GS           4
#define TILE_BYTES   8192
#define STAGE_BYTES  (3 * TILE_BYTES)              // 24 KB
#define GEMM_DSMEM   (GS * STAGE_BYTES + 1024)     // 99,328 B -> 2 CTAs/SM

static __device__ __forceinline__ void load_chunk(
    uint32_t st,
    const __half* __restrict__ Ah, const __half* __restrict__ Bh,
    const __half* __restrict__ Bl,
    int m0, int n0, int kk, int K, int tid)
{
    #pragma unroll
    for (int i = 0; i < 2; i++) {
        int ch  = tid + (i << 8);            // 0..511
        int rw  = ch >> 2;                   // row 0..127
        int c16 = ch & 3;                    // 16B chunk in 64B row
        uint32_t sw = (uint32_t)(rw << 6) +
                      (uint32_t)(((c16 ^ ((rw >> 1) & 3)) << 4));
        const char* sa = (const char*)(Ah + (size_t)(m0 + rw) * K + kk) + (c16 << 4);
        const char* sh = (const char*)(Bh + (size_t)(n0 + rw) * K + kk) + (c16 << 4);
        const char* sl = (const char*)(Bl + (size_t)(n0 + rw) * K + kk) + (c16 << 4);
        CP_ASYNC16(st + sw,                  sa);
        CP_ASYNC16(st + TILE_BYTES + sw,     sh);
        CP_ASYNC16(st + 2 * TILE_BYTES + sw, sl);
    }
}

__global__ __launch_bounds__(256, 2)
void hgemm2_kernel(const __half* __restrict__ A_hi,
                   const __half* __restrict__ B_hi, const __half* __restrict__ B_lo,
                   const float* __restrict__ bias, float* __restrict__ C,
                   int Nreal, int K)
{
    extern __shared__ char dynsmem[];
    const uint32_t tile0 = (smem_u32(dynsmem) + 1023u) & ~1023u;

    const int tid  = threadIdx.x;
    const int wid  = tid >> 5;
    const int lane = tid & 31;
    const int m0   = blockIdx.y * 128;
    const int n0   = blockIdx.x * 128;
    const int wm   = (wid & 1) * 64;
    const int wn   = (wid >> 1) * 32;

    const int r7 = lane & 7;
    const int q  = lane >> 3;
    const int rA  = ((q & 1) << 3) + r7;       // row-in-16 for ldmatrix
    const int cq  = q >> 1;                    // k16-half selector (0/1)
    const int sel = (rA >> 1) & 3;             // SW64 swizzle selector (per-lane)

    const int nch = K >> 5;

    float acc[4][4][4];
    #pragma unroll
    for (int a = 0; a < 4; a++)
        #pragma unroll
        for (int b = 0; b < 4; b++)
            #pragma unroll
            for (int c = 0; c < 4; c++) acc[a][b][c] = 0.0f;

    // prologue: chunks 0..2 into stages 0..2
    #pragma unroll
    for (int c = 0; c < GS - 1; c++) {
        load_chunk(tile0 + c * STAGE_BYTES, A_hi, B_hi, B_lo, m0, n0, c << 5, K, tid);
        CP_COMMIT();
    }

    for (int c = 0; c < nch; c++) {
        // chunk c resident when all but the newest min(2, nch-1-c) groups done
        if (c + 2 < nch)      { CP_WAIT2(); }
        else if (c + 1 < nch) { CP_WAIT1(); }
        else                  { CP_WAIT0(); }
        __syncthreads();

        // prefetch chunk c+3 into the stage freed by chunk c-1
        if (c + GS - 1 < nch)
            load_chunk(tile0 + ((c + GS - 1) & (GS - 1)) * STAGE_BYTES,
                       A_hi, B_hi, B_lo, m0, n0, (c + GS - 1) << 5, K, tid);
        CP_COMMIT();

        const uint32_t aB  = tile0 + (c & (GS - 1)) * STAGE_BYTES;
        const uint32_t bhB = aB + TILE_BYTES;
        const uint32_t blB = aB + 2 * TILE_BYTES;

        #pragma unroll
        for (int ks = 0; ks < 2; ks++) {
            uint32_t afr[4][4], bh[2][4], bl[2][4];
            const uint32_t chsw = (uint32_t)(((2 * ks + cq) ^ sel) << 4);
            // batch all 8 ldsm, then run 32 MMAs uninterrupted
            #pragma unroll
            for (int mt = 0; mt < 4; mt++)
                ldsm4(afr[mt], aB + (uint32_t)((wm + mt * 16 + rA) << 6) + chsw);
            #pragma unroll
            for (int ng = 0; ng < 2; ng++)
                ldsm4(bh[ng], bhB + (uint32_t)((wn + ng * 16 + rA) << 6) + chsw);
            #pragma unroll
            for (int ng = 0; ng < 2; ng++)
                ldsm4(bl[ng], blB + (uint32_t)((wn + ng * 16 + rA) << 6) + chsw);

            #pragma unroll
            for (int mt = 0; mt < 4; mt++)
                #pragma unroll
                for (int nt = 0; nt < 4; nt++) {
                    const int ng = nt >> 1, hl = nt & 1;
                    mma16816(acc[mt][nt], afr[mt], bh[ng][hl], bh[ng][hl + 2]);
                }
            #pragma unroll
            for (int mt = 0; mt < 4; mt++)
                #pragma unroll
                for (int nt = 0; nt < 4; nt++) {
                    const int ng = nt >> 1, hl = nt & 1;
                    mma16816(acc[mt][nt], afr[mt], bl[ng][hl], bl[ng][hl + 2]);
                }
        }
        __syncthreads();
    }

    // epilogue
    const int trow = lane >> 2;
    const int tcol = (lane & 3) * 2;
    #pragma unroll
    for (int mt = 0; mt < 4; mt++) {
        #pragma unroll
        for (int nt = 0; nt < 4; nt++) {
            const int col = n0 + wn + nt * 8 + tcol;
            if (col < Nreal) {
                const float2 b2 = *reinterpret_cast<const float2*>(bias + col);
                const int row0 = m0 + wm + mt * 16 + trow;
                float2 o0, o1;
                o0.x = acc[mt][nt][0] + b2.x;  o0.y = acc[mt][nt][1] + b2.y;
                o1.x = acc[mt][nt][2] + b2.x;  o1.y = acc[mt][nt][3] + b2.y;
                *reinterpret_cast<float2*>(C + (size_t)row0 * Nreal + col)       = o0;
                *reinterpret_cast<float2*>(C + (size_t)(row0 + 8) * Nreal + col) = o1;
            }
        }
    }
}

// ---------------------------------------------------------------------------
// fp32 -> fp16 (hi only)
// ---------------------------------------------------------------------------
__global__ void split_hi_kernel(const float* __restrict__ in,
                                __half* __restrict__ hi, int n4)
{
    int i = blockIdx.x * blockDim.x + threadIdx.x;
    if (i >= n4) return;
    float4 v = reinterpret_cast<const float4*>(in)[i];
    reinterpret_cast<__half2*>(hi)[2 * i + 0] =
        __halves2half2(__float2half_rn(v.x), __float2half_rn(v.y));
    reinterpret_cast<__half2*>(hi)[2 * i + 1] =
        __halves2half2(__float2half_rn(v.z), __float2half_rn(v.w));
}

// ---------------------------------------------------------------------------
// Transpose + split: W [K,N] fp32 -> hi/lo fp16 [Npad,K]
// ---------------------------------------------------------------------------
__global__ void tsplit_kernel(const float* __restrict__ W, int K, int N, int Npad,
                              __half* __restrict__ hi, __half* __restrict__ lo)
{
    __shared__ float tile[32][33];
    const int n0 = blockIdx.x * 32;
    const int k0 = blockIdx.y * 32;
    const int tx = threadIdx.x, ty = threadIdx.y;

    #pragma unroll
    for (int r = ty; r < 32; r += 8) {
        int n = n0 + tx, k = k0 + r;
        tile[r][tx] = (n < N) ? W[(size_t)k * N + n] : 0.0f;
    }
    __syncthreads();
    #pragma unroll
    for (int r = ty; r < 32; r += 8) {
        int n = n0 + r, k = k0 + tx;
        float v = tile[tx][r];
        __half h = __float2half_rn(v);
        hi[(size_t)n * K + k] = h;
        lo[(size_t)n * K + k] = __float2half_rn(v - __half2float(h));
    }
}

// ---------------------------------------------------------------------------
// YaRN RoPE in-place on fp32 qkv
// ---------------------------------------------------------------------------
__global__ void rope_kernel(const int* __restrict__ positions,
                            float* __restrict__ qkv)
{
    const int idx = blockIdx.x * blockDim.x + threadIdx.x;
    const int total = T_LEN * (N_HEADS + N_KV) * 32;
    if (idx >= total) return;

    const int d    = idx & 31;
    const int head = (idx >> 5) % (N_HEADS + N_KV);
    const int t    = idx / (32 * (N_HEADS + N_KV));

    const float p = (float)positions[t];
    const float lnB   = logf(150000.0f);
    const float freq  = expf(lnB * ((float)d / 32.0f));
    const float conc  = 0.1f * logf(32.0f) + 1.0f;
    const float twoPi = 6.283185307179586f;
    const float low   = 32.0f * logf(4096.0f / (32.0f * twoPi)) / lnB;
    const float high  = 32.0f * logf(4096.0f / (1.0f  * twoPi)) / lnB;
    float ramp = ((float)d - low) / (high - low);
    ramp = fminf(fmaxf(ramp, 0.0f), 1.0f);
    const float inv_freq = ramp / (32.0f * freq) + (1.0f - ramp) / freq;

    const float ang = p * inv_freq;
    const float c = cosf(ang) * conc;
    const float s = sinf(ang) * conc;

    float* base = qkv + (size_t)t * QKV_COLS + head * HEAD_DIM;
    const float x1 = base[d];
    const float x2 = base[d + 32];
    base[d]      = x1 * c - x2 * s;
    base[d + 32] = x2 * c + x1 * s;
}

// ---------------------------------------------------------------------------
// Sliding-window attention, 4-query register tiling.
// ---------------------------------------------------------------------------
#define ATT_ROWS 160
#define ATT_PAD  68
#define ATTN_DSMEM ((2 * ATT_ROWS * ATT_PAD + 8 * 4 * ATT_ROWS) * 4)

__global__ __launch_bounds__(256)
void attn_kernel(const float* __restrict__ qkv, const float* __restrict__ sinks,
                 __half* __restrict__ out_hi)
{
    extern __shared__ float sm[];
    float* K_s = sm;                                 // [160][68]
    float* V_s = K_s + ATT_ROWS * ATT_PAD;           // [160][68]
    float* P_s = V_s + ATT_ROWS * ATT_PAD;           // [8][4][160]

    const int tid  = threadIdx.x;
    const int warp = tid >> 5;
    const int lane = tid & 31;
    const int i0   = blockIdx.x * 32;
    const int kv   = blockIdx.y;
    const int h    = kv * 8 + warp;

    for (int idx = tid; idx < ATT_ROWS * 64; idx += 256) {
        const int r = idx >> 6, d = idx & 63;
        const int j = i0 - 127 + r;
        float kval = 0.0f, vval = 0.0f;
        if (j >= 0 && r < 159) {
            const float* src = qkv + (size_t)j * QKV_COLS + Q_SIZE + kv * 64 + d;
            kval = src[0];
            vval = src[KV_SIZE];
        }
        K_s[r * ATT_PAD + d] = kval;
        V_s[r * ATT_PAD + d] = vval;
    }
    __syncthreads();

    const float snk = sinks[h];
    float* pw = P_s + warp * (4 * ATT_ROWS);

    for (int g = 0; g < 8; g++) {
        const int qq0 = g * 4;

        float s[5][4];
        #pragma unroll
        for (int jj = 0; jj < 5; jj++)
            #pragma unroll
            for (int qq = 0; qq < 4; qq++) s[jj][qq] = 0.0f;

        const float* qbase = qkv + (size_t)(i0 + qq0) * QKV_COLS + h * 64;
        #pragma unroll
        for (int d4 = 0; d4 < 16; d4++) {
            float4 q4[4];
            #pragma unroll
            for (int qq = 0; qq < 4; qq++)
                q4[qq] = *reinterpret_cast<const float4*>(
                    qbase + (size_t)qq * QKV_COLS + d4 * 4);
            #pragma unroll
            for (int jj = 0; jj < 5; jj++) {
                int r = qq0 + jj * 32 + lane;
                if (r > 159) r = 159;
                const float4 kf = *reinterpret_cast<const float4*>(
                    K_s + r * ATT_PAD + d4 * 4);
                #pragma unroll
                for (int qq = 0; qq < 4; qq++)
                    s[jj][qq] += q4[qq].x * kf.x + q4[qq].y * kf.y +
                                 q4[qq].z * kf.z + q4[qq].w * kf.w;
            }
        }

        float inv[4];
        #pragma unroll
        for (int qq = 0; qq < 4; qq++) {
            float mm = snk;
            #pragma unroll
            for (int jj = 0; jj < 5; jj++) {
                const int R = jj * 32 + lane;
                const bool ok = (R >= qq) && (R <= qq + 127) &&
                                (i0 + qq0 - 127 + R >= 0);
                s[jj][qq] = ok ? s[jj][qq] * ATT_SCALE : -3.0e38f;
                mm = fmaxf(mm, s[jj][qq]);
            }
            #pragma unroll
            for (int off = 16; off > 0; off >>= 1)
                mm = fmaxf(mm, __shfl_xor_sync(0xFFFFFFFFu, mm, off));

            float dsum = 0.0f;
            #pragma unroll
            for (int jj = 0; jj < 5; jj++) {
                const float e = expf(s[jj][qq] - mm);
                pw[qq * ATT_ROWS + jj * 32 + lane] = e;
                dsum += e;
            }
            #pragma unroll
            for (int off = 16; off > 0; off >>= 1)
                dsum += __shfl_xor_sync(0xFFFFFFFFu, dsum, off);
            inv[qq] = 1.0f / (dsum + expf(snk - mm));
        }
        __syncwarp();

        float acc[4][2];
        #pragma unroll
        for (int qq = 0; qq < 4; qq++) { acc[qq][0] = 0.0f; acc[qq][1] = 0.0f; }

        #pragma unroll 4
        for (int R = 0; R < 131; R++) {
            const int r = qq0 + R;
            const float v0 = V_s[r * ATT_PAD + lane];
            const float v1 = V_s[r * ATT_PAD + lane + 32];
            #pragma unroll
            for (int qq = 0; qq < 4; qq++) {
                const float p = pw[qq * ATT_ROWS + R];
                acc[qq][0] += p * v0;
                acc[qq][1] += p * v1;
            }
        }

        #pragma unroll
        for (int qq = 0; qq < 4; qq++) {
            const size_t o = (size_t)(i0 + qq0 + qq) * Q_SIZE + h * 64 + lane;
            out_hi[o]      = __float2half_rn(acc[qq][0] * inv[qq]);
            out_hi[o + 32] = __float2half_rn(acc[qq][1] * inv[qq]);
        }
        __syncwarp();
    }
}

// ---------------------------------------------------------------------------
// Launch
// ---------------------------------------------------------------------------
extern "C" void kernel_launch(void* const* d_in, const int* in_sizes, int n_in,
                              void* d_out, int out_size)
{
    const int*   positions = (const int*)  d_in[0];
    const float* hidden    = (const float*)d_in[1];
    const float* W_qkv     = (const float*)d_in[2];
    const float* b_qkv     = (const float*)d_in[3];
    const float* W_o       = (const float*)d_in[4];
    const float* b_o       = (const float*)d_in[5];
    const float* sinks     = (const float*)d_in[6];
    float* out = (float*)d_out;

    float *qkv;
    __half *h_hi, *wq_hi, *wq_lo, *wo_hi, *wo_lo, *a_hi;
    cudaGetSymbolAddress((void**)&qkv,   g_qkv);
    cudaGetSymbolAddress((void**)&h_hi,  g_h_hi);
    cudaGetSymbolAddress((void**)&wq_hi, g_wq_hi);
    cudaGetSymbolAddress((void**)&wq_lo, g_wq_lo);
    cudaGetSymbolAddress((void**)&wo_hi, g_wo_hi);
    cudaGetSymbolAddress((void**)&wo_lo, g_wo_lo);
    cudaGetSymbolAddress((void**)&a_hi,  g_a_hi);

    static bool attr_done = false;
    if (!attr_done) {
        cudaFuncSetAttribute(hgemm2_kernel,
                             cudaFuncAttributeMaxDynamicSharedMemorySize, GEMM_DSMEM);
        cudaFuncSetAttribute(attn_kernel,
                             cudaFuncAttributeMaxDynamicSharedMemorySize, ATTN_DSMEM);
        attr_done = true;
    }

    // 0a) hidden -> fp16 hi
    {
        const int n4 = T_LEN * HIDDEN / 4;
        split_hi_kernel<<<(n4 + 255) / 256, 256>>>(hidden, h_hi, n4);
    }
    // 0b) transpose + split weights (hi/lo)
    {
        dim3 b(32, 8);
        dim3 g1(QKV_COLS / 32, HIDDEN / 32);
        tsplit_kernel<<<g1, b>>>(W_qkv, HIDDEN, QKV_COLS, QKV_COLS, wq_hi, wq_lo);
        dim3 g2(O_NPAD / 32, Q_SIZE / 32);
        tsplit_kernel<<<g2, b>>>(W_o, Q_SIZE, HIDDEN, O_NPAD, wo_hi, wo_lo);
    }
    // 1) QKV projection
    {
        dim3 grid(QKV_COLS / 128, T_LEN / 128);
        hgemm2_kernel<<<grid, 256, GEMM_DSMEM>>>(h_hi, wq_hi, wq_lo,
                                                 b_qkv, qkv, QKV_COLS, HIDDEN);
    }
    // 2) RoPE
    {
        const int total = T_LEN * (N_HEADS + N_KV) * 32;
        rope_kernel<<<(total + 255) / 256, 256>>>(positions, qkv);
    }
    // 3) attention
    {
        dim3 grid(T_LEN / 32, N_KV);
        attn_kernel<<<grid, 256, ATTN_DSMEM>>>(qkv, sinks, a_hi);
    }
    // 4) O projection
    {
        dim3 grid(O_NPAD / 128, T_LEN / 128);
        hgemm2_kernel<<<grid, 256, GEMM_DSMEM>>>(a_hi, wo_hi, wo_lo,
                                                 b_o, out, HIDDEN, Q_SIZE);
    }
}

// round 7
// speedup vs baseline: 1.3838x; 1.3838x over previous
#include <cuda_runtime.h>
#include <cuda_fp16.h>
#include <cstdint>
#include <cmath>

// ---------------------------------------------------------------------------
// GPT-OSS attention block on sm_100 (legacy mma.sync path).
// Round 7: single-pass fp16 GEMMs (A_hi * B_hi only — HMMA rate-bound, so
// halve the MMA count; error budget allows it). K-chunk 32, GS=6 stages
// (16KB each), 2 CTAs/SM. Attention with 4-query register tiling.
// ---------------------------------------------------------------------------

#define T_LEN      1536
#define HIDDEN     2880
#define N_HEADS    64
#define N_KV       8
#define HEAD_DIM   64
#define WINDOW     128
#define Q_SIZE     4096
#define KV_SIZE    512
#define QKV_COLS   5120
#define O_NPAD     2944
#define ATT_SCALE  0.125f

// ---------------- scratch ---------------------------------------------------
__device__ __align__(256) float  g_qkv   [(size_t)T_LEN * QKV_COLS];
__device__ __align__(256) __half g_h_hi  [(size_t)T_LEN * HIDDEN];
__device__ __align__(256) __half g_wq_hi [(size_t)QKV_COLS * HIDDEN];   // [N,K]
__device__ __align__(256) __half g_wo_hi [(size_t)O_NPAD * Q_SIZE];     // [N,K]
__device__ __align__(256) __half g_a_hi  [(size_t)T_LEN * Q_SIZE];

// ---------------- helpers ---------------------------------------------------
static __device__ __forceinline__ uint32_t smem_u32(const void* p) {
    uint32_t a;
    asm("{ .reg .u64 t; cvta.to.shared.u64 t, %1; cvt.u32.u64 %0, t; }"
        : "=r"(a) : "l"(p));
    return a;
}

#define CP_ASYNC16(dst, src) \
    asm volatile("cp.async.cg.shared.global [%0], [%1], 16;" :: "r"(dst), "l"(src))
#define CP_COMMIT() asm volatile("cp.async.commit_group;")
#define CP_WAITG()  asm volatile("cp.async.wait_group 4;")   // GS-2

static __device__ __forceinline__ void ldsm4(uint32_t* r, uint32_t addr) {
    asm volatile("ldmatrix.sync.aligned.m8n8.x4.shared.b16 {%0,%1,%2,%3}, [%4];"
                 : "=r"(r[0]), "=r"(r[1]), "=r"(r[2]), "=r"(r[3]) : "r"(addr));
}

static __device__ __forceinline__ void mma16816(float* d, const uint32_t* a,
                                                uint32_t b0, uint32_t b1) {
    asm volatile("mma.sync.aligned.m16n8k16.row.col.f32.f16.f16.f32 "
                 "{%0,%1,%2,%3}, {%4,%5,%6,%7}, {%8,%9}, {%0,%1,%2,%3};"
                 : "+f"(d[0]), "+f"(d[1]), "+f"(d[2]), "+f"(d[3])
                 : "r"(a[0]), "r"(a[1]), "r"(a[2]), "r"(a[3]), "r"(b0), "r"(b1));
}

// ---------------------------------------------------------------------------
// 1-pass fp16 HMMA GEMM:  C[M,Nreal] = A_hi[M,K] @ B_hi[Npad,K]^T + bias
// CTA 128x128, K-chunk 32, stage = {A 8K, B 8K}, GS=6 stages, 256 threads
// (8 warps of 64x32), 2 CTAs/SM. Rows are 64B -> SW64 swizzle.
// ---------------------------------------------------------------------------
#define GS           6
#define TILE_BYTES   8192
#define STAGE_BYTES  (2 * TILE_BYTES)              // 16 KB
#define GEMM_DSMEM   (GS * STAGE_BYTES + 1024)     // 99,328 B -> 2 CTAs/SM

static __device__ __forceinline__ void load_chunk(
    uint32_t st,
    const __half* __restrict__ Ah, const __half* __restrict__ Bh,
    int m0, int n0, int kk, int K, int tid)
{
    #pragma unroll
    for (int i = 0; i < 2; i++) {
        int ch  = tid + (i << 8);            // 0..511
        int rw  = ch >> 2;                   // row 0..127
        int c16 = ch & 3;                    // 16B chunk in 64B row
        uint32_t sw = (uint32_t)(rw << 6) +
                      (uint32_t)(((c16 ^ ((rw >> 1) & 3)) << 4));
        const char* sa = (const char*)(Ah + (size_t)(m0 + rw) * K + kk) + (c16 << 4);
        const char* sb = (const char*)(Bh + (size_t)(n0 + rw) * K + kk) + (c16 << 4);
        CP_ASYNC16(st + sw,              sa);
        CP_ASYNC16(st + TILE_BYTES + sw, sb);
    }
}

__global__ __launch_bounds__(256, 2)
void hgemm1_kernel(const __half* __restrict__ A_hi,
                   const __half* __restrict__ B_hi,
                   const float* __restrict__ bias, float* __restrict__ C,
                   int Nreal, int K)
{
    extern __shared__ char dynsmem[];
    const uint32_t tile0 = (smem_u32(dynsmem) + 1023u) & ~1023u;

    const int tid  = threadIdx.x;
    const int wid  = tid >> 5;
    const int lane = tid & 31;
    const int m0   = blockIdx.y * 128;
    const int n0   = blockIdx.x * 128;
    const int wm   = (wid & 1) * 64;
    const int wn   = (wid >> 1) * 32;

    const int r7 = lane & 7;
    const int q  = lane >> 3;
    const int rA  = ((q & 1) << 3) + r7;       // row-in-16 for ldmatrix
    const int cq  = q >> 1;                    // k16-half selector (0/1)
    const int sel = (rA >> 1) & 3;             // SW64 swizzle selector

    const int nch = K >> 5;

    float acc[4][4][4];
    #pragma unroll
    for (int a = 0; a < 4; a++)
        #pragma unroll
        for (int b = 0; b < 4; b++)
            #pragma unroll
            for (int c = 0; c < 4; c++) acc[a][b][c] = 0.0f;

    // prologue: chunks 0..GS-2 into stages 0..GS-2
    #pragma unroll
    for (int c = 0; c < GS - 1; c++) {
        load_chunk(tile0 + c * STAGE_BYTES, A_hi, B_hi, m0, n0, c << 5, K, tid);
        CP_COMMIT();
    }

    int stage_c = 0, stage_p = GS - 1;
    for (int c = 0; c < nch; c++) {
        CP_WAITG();                  // chunk c resident (<=GS-2 newer pending)
        __syncthreads();

        // prefetch chunk c+GS-1 into the stage freed by chunk c-1
        if (c + GS - 1 < nch)
            load_chunk(tile0 + stage_p * STAGE_BYTES, A_hi, B_hi,
                       m0, n0, (c + GS - 1) << 5, K, tid);
        CP_COMMIT();
        if (++stage_p == GS) stage_p = 0;

        const uint32_t aB = tile0 + stage_c * STAGE_BYTES;
        const uint32_t bB = aB + TILE_BYTES;
        if (++stage_c == GS) stage_c = 0;

        #pragma unroll
        for (int ks = 0; ks < 2; ks++) {
            uint32_t afr[4][4], bfr[2][4];
            const uint32_t chsw = (uint32_t)(((2 * ks + cq) ^ sel) << 4);
            #pragma unroll
            for (int mt = 0; mt < 4; mt++)
                ldsm4(afr[mt], aB + (uint32_t)((wm + mt * 16 + rA) << 6) + chsw);
            #pragma unroll
            for (int ng = 0; ng < 2; ng++)
                ldsm4(bfr[ng], bB + (uint32_t)((wn + ng * 16 + rA) << 6) + chsw);

            #pragma unroll
            for (int mt = 0; mt < 4; mt++)
                #pragma unroll
                for (int nt = 0; nt < 4; nt++) {
                    const int ng = nt >> 1, hl = nt & 1;
                    mma16816(acc[mt][nt], afr[mt], bfr[ng][hl], bfr[ng][hl + 2]);
                }
        }
        __syncthreads();
    }

    // epilogue
    const int trow = lane >> 2;
    const int tcol = (lane & 3) * 2;
    #pragma unroll
    for (int mt = 0; mt < 4; mt++) {
        #pragma unroll
        for (int nt = 0; nt < 4; nt++) {
            const int col = n0 + wn + nt * 8 + tcol;
            if (col < Nreal) {
                const float2 b2 = *reinterpret_cast<const float2*>(bias + col);
                const int row0 = m0 + wm + mt * 16 + trow;
                float2 o0, o1;
                o0.x = acc[mt][nt][0] + b2.x;  o0.y = acc[mt][nt][1] + b2.y;
                o1.x = acc[mt][nt][2] + b2.x;  o1.y = acc[mt][nt][3] + b2.y;
                *reinterpret_cast<float2*>(C + (size_t)row0 * Nreal + col)       = o0;
                *reinterpret_cast<float2*>(C + (size_t)(row0 + 8) * Nreal + col) = o1;
            }
        }
    }
}

// ---------------------------------------------------------------------------
// fp32 -> fp16 (hi only)
// ---------------------------------------------------------------------------
__global__ void split_hi_kernel(const float* __restrict__ in,
                                __half* __restrict__ hi, int n4)
{
    int i = blockIdx.x * blockDim.x + threadIdx.x;
    if (i >= n4) return;
    float4 v = reinterpret_cast<const float4*>(in)[i];
    reinterpret_cast<__half2*>(hi)[2 * i + 0] =
        __halves2half2(__float2half_rn(v.x), __float2half_rn(v.y));
    reinterpret_cast<__half2*>(hi)[2 * i + 1] =
        __halves2half2(__float2half_rn(v.z), __float2half_rn(v.w));
}

// ---------------------------------------------------------------------------
// Transpose: W [K,N] fp32 -> hi fp16 [Npad,K] (rows >= N zeroed)
// ---------------------------------------------------------------------------
__global__ void thi_kernel(const float* __restrict__ W, int K, int N, int Npad,
                           __half* __restrict__ hi)
{
    __shared__ float tile[32][33];
    const int n0 = blockIdx.x * 32;
    const int k0 = blockIdx.y * 32;
    const int tx = threadIdx.x, ty = threadIdx.y;

    #pragma unroll
    for (int r = ty; r < 32; r += 8) {
        int n = n0 + tx, k = k0 + r;
        tile[r][tx] = (n < N) ? W[(size_t)k * N + n] : 0.0f;
    }
    __syncthreads();
    #pragma unroll
    for (int r = ty; r < 32; r += 8) {
        int n = n0 + r, k = k0 + tx;
        hi[(size_t)n * K + k] = __float2half_rn(tile[tx][r]);
    }
}

// ---------------------------------------------------------------------------
// YaRN RoPE in-place on fp32 qkv
// ---------------------------------------------------------------------------
__global__ void rope_kernel(const int* __restrict__ positions,
                            float* __restrict__ qkv)
{
    const int idx = blockIdx.x * blockDim.x + threadIdx.x;
    const int total = T_LEN * (N_HEADS + N_KV) * 32;
    if (idx >= total) return;

    const int d    = idx & 31;
    const int head = (idx >> 5) % (N_HEADS + N_KV);
    const int t    = idx / (32 * (N_HEADS + N_KV));

    const float p = (float)positions[t];
    const float lnB   = logf(150000.0f);
    const float freq  = expf(lnB * ((float)d / 32.0f));
    const float conc  = 0.1f * logf(32.0f) + 1.0f;
    const float twoPi = 6.283185307179586f;
    const float low   = 32.0f * logf(4096.0f / (32.0f * twoPi)) / lnB;
    const float high  = 32.0f * logf(4096.0f / (1.0f  * twoPi)) / lnB;
    float ramp = ((float)d - low) / (high - low);
    ramp = fminf(fmaxf(ramp, 0.0f), 1.0f);
    const float inv_freq = ramp / (32.0f * freq) + (1.0f - ramp) / freq;

    const float ang = p * inv_freq;
    const float c = cosf(ang) * conc;
    const float s = sinf(ang) * conc;

    float* base = qkv + (size_t)t * QKV_COLS + head * HEAD_DIM;
    const float x1 = base[d];
    const float x2 = base[d + 32];
    base[d]      = x1 * c - x2 * s;
    base[d + 32] = x2 * c + x1 * s;
}

// ---------------------------------------------------------------------------
// Sliding-window attention, 4-query register tiling.
// ---------------------------------------------------------------------------
#define ATT_ROWS 160
#define ATT_PAD  68
#define ATTN_DSMEM ((2 * ATT_ROWS * ATT_PAD + 8 * 4 * ATT_ROWS) * 4)

__global__ __launch_bounds__(256)
void attn_kernel(const float* __restrict__ qkv, const float* __restrict__ sinks,
                 __half* __restrict__ out_hi)
{
    extern __shared__ float sm[];
    float* K_s = sm;                                 // [160][68]
    float* V_s = K_s + ATT_ROWS * ATT_PAD;           // [160][68]
    float* P_s = V_s + ATT_ROWS * ATT_PAD;           // [8][4][160]

    const int tid  = threadIdx.x;
    const int warp = tid >> 5;
    const int lane = tid & 31;
    const int i0   = blockIdx.x * 32;
    const int kv   = blockIdx.y;
    const int h    = kv * 8 + warp;

    for (int idx = tid; idx < ATT_ROWS * 64; idx += 256) {
        const int r = idx >> 6, d = idx & 63;
        const int j = i0 - 127 + r;
        float kval = 0.0f, vval = 0.0f;
        if (j >= 0 && r < 159) {
            const float* src = qkv + (size_t)j * QKV_COLS + Q_SIZE + kv * 64 + d;
            kval = src[0];
            vval = src[KV_SIZE];
        }
        K_s[r * ATT_PAD + d] = kval;
        V_s[r * ATT_PAD + d] = vval;
    }
    __syncthreads();

    const float snk = sinks[h];
    float* pw = P_s + warp * (4 * ATT_ROWS);

    for (int g = 0; g < 8; g++) {
        const int qq0 = g * 4;

        float s[5][4];
        #pragma unroll
        for (int jj = 0; jj < 5; jj++)
            #pragma unroll
            for (int qq = 0; qq < 4; qq++) s[jj][qq] = 0.0f;

        const float* qbase = qkv + (size_t)(i0 + qq0) * QKV_COLS + h * 64;
        #pragma unroll
        for (int d4 = 0; d4 < 16; d4++) {
            float4 q4[4];
            #pragma unroll
            for (int qq = 0; qq < 4; qq++)
                q4[qq] = *reinterpret_cast<const float4*>(
                    qbase + (size_t)qq * QKV_COLS + d4 * 4);
            #pragma unroll
            for (int jj = 0; jj < 5; jj++) {
                int r = qq0 + jj * 32 + lane;
                if (r > 159) r = 159;
                const float4 kf = *reinterpret_cast<const float4*>(
                    K_s + r * ATT_PAD + d4 * 4);
                #pragma unroll
                for (int qq = 0; qq < 4; qq++)
                    s[jj][qq] += q4[qq].x * kf.x + q4[qq].y * kf.y +
                                 q4[qq].z * kf.z + q4[qq].w * kf.w;
            }
        }

        float inv[4];
        #pragma unroll
        for (int qq = 0; qq < 4; qq++) {
            float mm = snk;
            #pragma unroll
            for (int jj = 0; jj < 5; jj++) {
                const int R = jj * 32 + lane;
                const bool ok = (R >= qq) && (R <= qq + 127) &&
                                (i0 + qq0 - 127 + R >= 0);
                s[jj][qq] = ok ? s[jj][qq] * ATT_SCALE : -3.0e38f;
                mm = fmaxf(mm, s[jj][qq]);
            }
            #pragma unroll
            for (int off = 16; off > 0; off >>= 1)
                mm = fmaxf(mm, __shfl_xor_sync(0xFFFFFFFFu, mm, off));

            float dsum = 0.0f;
            #pragma unroll
            for (int jj = 0; jj < 5; jj++) {
                const float e = expf(s[jj][qq] - mm);
                pw[qq * ATT_ROWS + jj * 32 + lane] = e;
                dsum += e;
            }
            #pragma unroll
            for (int off = 16; off > 0; off >>= 1)
                dsum += __shfl_xor_sync(0xFFFFFFFFu, dsum, off);
            inv[qq] = 1.0f / (dsum + expf(snk - mm));
        }
        __syncwarp();

        float acc[4][2];
        #pragma unroll
        for (int qq = 0; qq < 4; qq++) { acc[qq][0] = 0.0f; acc[qq][1] = 0.0f; }

        #pragma unroll 4
        for (int R = 0; R < 131; R++) {
            const int r = qq0 + R;
            const float v0 = V_s[r * ATT_PAD + lane];
            const float v1 = V_s[r * ATT_PAD + lane + 32];
            #pragma unroll
            for (int qq = 0; qq < 4; qq++) {
                const float p = pw[qq * ATT_ROWS + R];
                acc[qq][0] += p * v0;
                acc[qq][1] += p * v1;
            }
        }

        #pragma unroll
        for (int qq = 0; qq < 4; qq++) {
            const size_t o = (size_t)(i0 + qq0 + qq) * Q_SIZE + h * 64 + lane;
            out_hi[o]      = __float2half_rn(acc[qq][0] * inv[qq]);
            out_hi[o + 32] = __float2half_rn(acc[qq][1] * inv[qq]);
        }
        __syncwarp();
    }
}

// ---------------------------------------------------------------------------
// Launch
// ---------------------------------------------------------------------------
extern "C" void kernel_launch(void* const* d_in, const int* in_sizes, int n_in,
                              void* d_out, int out_size)
{
    const int*   positions = (const int*)  d_in[0];
    const float* hidden    = (const float*)d_in[1];
    const float* W_qkv     = (const float*)d_in[2];
    const float* b_qkv     = (const float*)d_in[3];
    const float* W_o       = (const float*)d_in[4];
    const float* b_o       = (const float*)d_in[5];
    const float* sinks     = (const float*)d_in[6];
    float* out = (float*)d_out;

    float *qkv;
    __half *h_hi, *wq_hi, *wo_hi, *a_hi;
    cudaGetSymbolAddress((void**)&qkv,   g_qkv);
    cudaGetSymbolAddress((void**)&h_hi,  g_h_hi);
    cudaGetSymbolAddress((void**)&wq_hi, g_wq_hi);
    cudaGetSymbolAddress((void**)&wo_hi, g_wo_hi);
    cudaGetSymbolAddress((void**)&a_hi,  g_a_hi);

    static bool attr_done = false;
    if (!attr_done) {
        cudaFuncSetAttribute(hgemm1_kernel,
                             cudaFuncAttributeMaxDynamicSharedMemorySize, GEMM_DSMEM);
        cudaFuncSetAttribute(attn_kernel,
                             cudaFuncAttributeMaxDynamicSharedMemorySize, ATTN_DSMEM);
        attr_done = true;
    }

    // 0a) hidden -> fp16 hi
    {
        const int n4 = T_LEN * HIDDEN / 4;
        split_hi_kernel<<<(n4 + 255) / 256, 256>>>(hidden, h_hi, n4);
    }
    // 0b) transpose weights (hi only)
    {
        dim3 b(32, 8);
        dim3 g1(QKV_COLS / 32, HIDDEN / 32);
        thi_kernel<<<g1, b>>>(W_qkv, HIDDEN, QKV_COLS, QKV_COLS, wq_hi);
        dim3 g2(O_NPAD / 32, Q_SIZE / 32);
        thi_kernel<<<g2, b>>>(W_o, Q_SIZE, HIDDEN, O_NPAD, wo_hi);
    }
    // 1) QKV projection
    {
        dim3 grid(QKV_COLS / 128, T_LEN / 128);
        hgemm1_kernel<<<grid, 256, GEMM_DSMEM>>>(h_hi, wq_hi,
                                                 b_qkv, qkv, QKV_COLS, HIDDEN);
    }
    // 2) RoPE
    {
        const int total = T_LEN * (N_HEADS + N_KV) * 32;
        rope_kernel<<<(total + 255) / 256, 256>>>(positions, qkv);
    }
    // 3) attention
    {
        dim3 grid(T_LEN / 32, N_KV);
        attn_kernel<<<grid, 256, ATTN_DSMEM>>>(qkv, sinks, a_hi);
    }
    // 4) O projection
    {
        dim3 grid(O_NPAD / 128, T_LEN / 128);
        hgemm1_kernel<<<grid, 256, GEMM_DSMEM>>>(a_hi, wo_hi,
                                                 b_o, out, HIDDEN, Q_SIZE);
    }
}

// round 8
// speedup vs baseline: 1.7241x; 1.2459x over previous
#include <cuda_runtime.h>
#include <cuda_fp16.h>
#include <cstdint>
#include <cmath>

// ---------------------------------------------------------------------------
// GPT-OSS attention block on sm_100 (legacy mma.sync path).
// Round 8: tensor-core flash attention (fp16 QK + PV via mma.sync, fp32
// online softmax with sink). GEMMs unchanged from R7 (at fp32-accum HMMA
// ceiling).
// ---------------------------------------------------------------------------

#define T_LEN      1536
#define HIDDEN     2880
#define N_HEADS    64
#define N_KV       8
#define HEAD_DIM   64
#define WINDOW     128
#define Q_SIZE     4096
#define KV_SIZE    512
#define QKV_COLS   5120
#define O_NPAD     2944
#define ATT_SCALE  0.125f

// ---------------- scratch ---------------------------------------------------
__device__ __align__(256) float  g_qkv   [(size_t)T_LEN * QKV_COLS];
__device__ __align__(256) __half g_h_hi  [(size_t)T_LEN * HIDDEN];
__device__ __align__(256) __half g_wq_hi [(size_t)QKV_COLS * HIDDEN];   // [N,K]
__device__ __align__(256) __half g_wo_hi [(size_t)O_NPAD * Q_SIZE];     // [N,K]
__device__ __align__(256) __half g_a_hi  [(size_t)T_LEN * Q_SIZE];

// ---------------- helpers ---------------------------------------------------
static __device__ __forceinline__ uint32_t smem_u32(const void* p) {
    uint32_t a;
    asm("{ .reg .u64 t; cvta.to.shared.u64 t, %1; cvt.u32.u64 %0, t; }"
        : "=r"(a) : "l"(p));
    return a;
}

#define CP_ASYNC16(dst, src) \
    asm volatile("cp.async.cg.shared.global [%0], [%1], 16;" :: "r"(dst), "l"(src))
#define CP_COMMIT() asm volatile("cp.async.commit_group;")
#define CP_WAITG()  asm volatile("cp.async.wait_group 4;")   // GS-2

static __device__ __forceinline__ void ldsm4(uint32_t* r, uint32_t addr) {
    asm volatile("ldmatrix.sync.aligned.m8n8.x4.shared.b16 {%0,%1,%2,%3}, [%4];"
                 : "=r"(r[0]), "=r"(r[1]), "=r"(r[2]), "=r"(r[3]) : "r"(addr));
}

static __device__ __forceinline__ void ldsm4t(uint32_t* r, uint32_t addr) {
    asm volatile("ldmatrix.sync.aligned.m8n8.x4.trans.shared.b16 {%0,%1,%2,%3}, [%4];"
                 : "=r"(r[0]), "=r"(r[1]), "=r"(r[2]), "=r"(r[3]) : "r"(addr));
}

static __device__ __forceinline__ void mma16816(float* d, const uint32_t* a,
                                                uint32_t b0, uint32_t b1) {
    asm volatile("mma.sync.aligned.m16n8k16.row.col.f32.f16.f16.f32 "
                 "{%0,%1,%2,%3}, {%4,%5,%6,%7}, {%8,%9}, {%0,%1,%2,%3};"
                 : "+f"(d[0]), "+f"(d[1]), "+f"(d[2]), "+f"(d[3])
                 : "r"(a[0]), "r"(a[1]), "r"(a[2]), "r"(a[3]), "r"(b0), "r"(b1));
}

// ---------------------------------------------------------------------------
// 1-pass fp16 HMMA GEMM (unchanged from R7; at fp32-accum HMMA ceiling)
// ---------------------------------------------------------------------------
#define GS           6
#define TILE_BYTES   8192
#define STAGE_BYTES  (2 * TILE_BYTES)
#define GEMM_DSMEM   (GS * STAGE_BYTES + 1024)

static __device__ __forceinline__ void load_chunk(
    uint32_t st,
    const __half* __restrict__ Ah, const __half* __restrict__ Bh,
    int m0, int n0, int kk, int K, int tid)
{
    #pragma unroll
    for (int i = 0; i < 2; i++) {
        int ch  = tid + (i << 8);
        int rw  = ch >> 2;
        int c16 = ch & 3;
        uint32_t sw = (uint32_t)(rw << 6) +
                      (uint32_t)(((c16 ^ ((rw >> 1) & 3)) << 4));
        const char* sa = (const char*)(Ah + (size_t)(m0 + rw) * K + kk) + (c16 << 4);
        const char* sb = (const char*)(Bh + (size_t)(n0 + rw) * K + kk) + (c16 << 4);
        CP_ASYNC16(st + sw,              sa);
        CP_ASYNC16(st + TILE_BYTES + sw, sb);
    }
}

__global__ __launch_bounds__(256, 2)
void hgemm1_kernel(const __half* __restrict__ A_hi,
                   const __half* __restrict__ B_hi,
                   const float* __restrict__ bias, float* __restrict__ C,
                   int Nreal, int K)
{
    extern __shared__ char dynsmem[];
    const uint32_t tile0 = (smem_u32(dynsmem) + 1023u) & ~1023u;

    const int tid  = threadIdx.x;
    const int wid  = tid >> 5;
    const int lane = tid & 31;
    const int m0   = blockIdx.y * 128;
    const int n0   = blockIdx.x * 128;
    const int wm   = (wid & 1) * 64;
    const int wn   = (wid >> 1) * 32;

    const int r7 = lane & 7;
    const int q  = lane >> 3;
    const int rA  = ((q & 1) << 3) + r7;
    const int cq  = q >> 1;
    const int sel = (rA >> 1) & 3;

    const int nch = K >> 5;

    float acc[4][4][4];
    #pragma unroll
    for (int a = 0; a < 4; a++)
        #pragma unroll
        for (int b = 0; b < 4; b++)
            #pragma unroll
            for (int c = 0; c < 4; c++) acc[a][b][c] = 0.0f;

    #pragma unroll
    for (int c = 0; c < GS - 1; c++) {
        load_chunk(tile0 + c * STAGE_BYTES, A_hi, B_hi, m0, n0, c << 5, K, tid);
        CP_COMMIT();
    }

    int stage_c = 0, stage_p = GS - 1;
    for (int c = 0; c < nch; c++) {
        CP_WAITG();
        __syncthreads();

        if (c + GS - 1 < nch)
            load_chunk(tile0 + stage_p * STAGE_BYTES, A_hi, B_hi,
                       m0, n0, (c + GS - 1) << 5, K, tid);
        CP_COMMIT();
        if (++stage_p == GS) stage_p = 0;

        const uint32_t aB = tile0 + stage_c * STAGE_BYTES;
        const uint32_t bB = aB + TILE_BYTES;
        if (++stage_c == GS) stage_c = 0;

        #pragma unroll
        for (int ks = 0; ks < 2; ks++) {
            uint32_t afr[4][4], bfr[2][4];
            const uint32_t chsw = (uint32_t)(((2 * ks + cq) ^ sel) << 4);
            #pragma unroll
            for (int mt = 0; mt < 4; mt++)
                ldsm4(afr[mt], aB + (uint32_t)((wm + mt * 16 + rA) << 6) + chsw);
            #pragma unroll
            for (int ng = 0; ng < 2; ng++)
                ldsm4(bfr[ng], bB + (uint32_t)((wn + ng * 16 + rA) << 6) + chsw);

            #pragma unroll
            for (int mt = 0; mt < 4; mt++)
                #pragma unroll
                for (int nt = 0; nt < 4; nt++) {
                    const int ng = nt >> 1, hl = nt & 1;
                    mma16816(acc[mt][nt], afr[mt], bfr[ng][hl], bfr[ng][hl + 2]);
                }
        }
        __syncthreads();
    }

    const int trow = lane >> 2;
    const int tcol = (lane & 3) * 2;
    #pragma unroll
    for (int mt = 0; mt < 4; mt++) {
        #pragma unroll
        for (int nt = 0; nt < 4; nt++) {
            const int col = n0 + wn + nt * 8 + tcol;
            if (col < Nreal) {
                const float2 b2 = *reinterpret_cast<const float2*>(bias + col);
                const int row0 = m0 + wm + mt * 16 + trow;
                float2 o0, o1;
                o0.x = acc[mt][nt][0] + b2.x;  o0.y = acc[mt][nt][1] + b2.y;
                o1.x = acc[mt][nt][2] + b2.x;  o1.y = acc[mt][nt][3] + b2.y;
                *reinterpret_cast<float2*>(C + (size_t)row0 * Nreal + col)       = o0;
                *reinterpret_cast<float2*>(C + (size_t)(row0 + 8) * Nreal + col) = o1;
            }
        }
    }
}

// ---------------------------------------------------------------------------
// fp32 -> fp16 (hi only)
// ---------------------------------------------------------------------------
__global__ void split_hi_kernel(const float* __restrict__ in,
                                __half* __restrict__ hi, int n4)
{
    int i = blockIdx.x * blockDim.x + threadIdx.x;
    if (i >= n4) return;
    float4 v = reinterpret_cast<const float4*>(in)[i];
    reinterpret_cast<__half2*>(hi)[2 * i + 0] =
        __halves2half2(__float2half_rn(v.x), __float2half_rn(v.y));
    reinterpret_cast<__half2*>(hi)[2 * i + 1] =
        __halves2half2(__float2half_rn(v.z), __float2half_rn(v.w));
}

// ---------------------------------------------------------------------------
// Transpose: W [K,N] fp32 -> hi fp16 [Npad,K]
// ---------------------------------------------------------------------------
__global__ void thi_kernel(const float* __restrict__ W, int K, int N, int Npad,
                           __half* __restrict__ hi)
{
    __shared__ float tile[32][33];
    const int n0 = blockIdx.x * 32;
    const int k0 = blockIdx.y * 32;
    const int tx = threadIdx.x, ty = threadIdx.y;

    #pragma unroll
    for (int r = ty; r < 32; r += 8) {
        int n = n0 + tx, k = k0 + r;
        tile[r][tx] = (n < N) ? W[(size_t)k * N + n] : 0.0f;
    }
    __syncthreads();
    #pragma unroll
    for (int r = ty; r < 32; r += 8) {
        int n = n0 + r, k = k0 + tx;
        hi[(size_t)n * K + k] = __float2half_rn(tile[tx][r]);
    }
}

// ---------------------------------------------------------------------------
// YaRN RoPE in-place on fp32 qkv
// ---------------------------------------------------------------------------
__global__ void rope_kernel(const int* __restrict__ positions,
                            float* __restrict__ qkv)
{
    const int idx = blockIdx.x * blockDim.x + threadIdx.x;
    const int total = T_LEN * (N_HEADS + N_KV) * 32;
    if (idx >= total) return;

    const int d    = idx & 31;
    const int head = (idx >> 5) % (N_HEADS + N_KV);
    const int t    = idx / (32 * (N_HEADS + N_KV));

    const float p = (float)positions[t];
    const float lnB   = logf(150000.0f);
    const float freq  = expf(lnB * ((float)d / 32.0f));
    const float conc  = 0.1f * logf(32.0f) + 1.0f;
    const float twoPi = 6.283185307179586f;
    const float low   = 32.0f * logf(4096.0f / (32.0f * twoPi)) / lnB;
    const float high  = 32.0f * logf(4096.0f / (1.0f  * twoPi)) / lnB;
    float ramp = ((float)d - low) / (high - low);
    ramp = fminf(fmaxf(ramp, 0.0f), 1.0f);
    const float inv_freq = ramp / (32.0f * freq) + (1.0f - ramp) / freq;

    const float ang = p * inv_freq;
    const float c = cosf(ang) * conc;
    const float s = sinf(ang) * conc;

    float* base = qkv + (size_t)t * QKV_COLS + head * HEAD_DIM;
    const float x1 = base[d];
    const float x2 = base[d + 32];
    base[d]      = x1 * c - x2 * s;
    base[d + 32] = x2 * c + x1 * s;
}

// ---------------------------------------------------------------------------
// Tensor-core flash attention with sink.
// CTA = (64-query block, kv head); 8 warps, warp = q-head.
// K/V staged fp16 SW128-swizzled in smem (192 rows); per warp: 4 tasks of
// 16 queries; online softmax fp32; P kept as fp16 A-frags; PV via
// ldmatrix.trans on V.
// ---------------------------------------------------------------------------
#define AROWS       192
#define ATTN_DSMEM  65536   // K 24K + V 24K + 8 x 2K Q scratch

__global__ __launch_bounds__(256, 2)
void attn_mma_kernel(const float* __restrict__ qkv,
                     const float* __restrict__ sinks,
                     __half* __restrict__ out_hi)
{
    extern __shared__ char asmem[];
    const uint32_t sbase = smem_u32(asmem);
    const uint32_t Ks = sbase;
    const uint32_t Vs = sbase + 24576;

    const int tid  = threadIdx.x;
    const int warp = tid >> 5;
    const int lane = tid & 31;
    const int i0   = blockIdx.x * 64;
    const int kv   = blockIdx.y;
    const int h    = kv * 8 + warp;
    const uint32_t Qs = sbase + 49152 + warp * 2048;

    // ---- stage K/V rows j = i0-128+r (r=0..191), fp16 swizzled ----
    for (int idx = tid; idx < AROWS * 32; idx += 256) {
        const int r = idx >> 5, d2 = idx & 31;
        const int j = i0 - 128 + r;
        float2 kf = make_float2(0.f, 0.f), vf = make_float2(0.f, 0.f);
        if (j >= 0) {
            const float* src = qkv + (size_t)j * QKV_COLS + Q_SIZE + kv * 64 + 2 * d2;
            kf = *reinterpret_cast<const float2*>(src);
            vf = *reinterpret_cast<const float2*>(src + KV_SIZE);
        }
        const uint32_t sw = (uint32_t)(r * 128) +
                            ((uint32_t)((d2 >> 2) ^ (r & 7)) << 4) + (d2 & 3) * 4;
        *reinterpret_cast<__half2*>(asmem + sw)         = __floats2half2_rn(kf.x, kf.y);
        *reinterpret_cast<__half2*>(asmem + 24576 + sw) = __floats2half2_rn(vf.x, vf.y);
    }
    __syncthreads();

    const float snk = sinks[h];
    const int r7 = lane & 7;
    const int qq = lane >> 3;
    const int rA = ((qq & 1) << 3) + r7;      // ldmatrix row-in-16
    const int cq = qq >> 1;                   // k16-half selector
    const int vrow_l = (lane & 7) + ((lane >> 4) << 3);   // V-trans row
    const int vnsel  = (lane >> 3) & 1;                   // V-trans n-chunk

    for (int mt = 0; mt < 4; mt++) {
        const int i_base = i0 + mt * 16;

        // stage this task's Q tile [16][64] fp16 swizzled
        __syncwarp();
        for (int e = lane; e < 512; e += 32) {
            const int r = e >> 5, d2 = e & 31;
            const float2 qf = *reinterpret_cast<const float2*>(
                qkv + (size_t)(i_base + r) * QKV_COLS + h * 64 + 2 * d2);
            const uint32_t sw = (uint32_t)(r * 128) +
                                ((uint32_t)((d2 >> 2) ^ (r & 7)) << 4) + (d2 & 3) * 4;
            *reinterpret_cast<__half2*>(asmem + 49152 + warp * 2048 + sw) =
                __floats2half2_rn(qf.x, qf.y);
        }
        __syncwarp();

        uint32_t aQ[4][4];
        #pragma unroll
        for (int ks = 0; ks < 4; ks++)
            ldsm4(aQ[ks], Qs + (uint32_t)(rA * 128) +
                          ((uint32_t)(((2 * ks + cq) ^ r7)) << 4));

        float m0 = snk, m1 = snk, l0 = 0.f, l1 = 0.f;
        float ofr[8][4];
        #pragma unroll
        for (int dn = 0; dn < 8; dn++)
            #pragma unroll
            for (int c = 0; c < 4; c++) ofr[dn][c] = 0.f;

        const int b_lo = (mt >= 2) ? 1 : 0;
        for (int bb = 0; bb < 5; bb++) {
            const int b = b_lo + bb;

            // ---- S = Q K^T (32-key block) ----
            float sf[4][4];
            #pragma unroll
            for (int nt = 0; nt < 4; nt++)
                #pragma unroll
                for (int c = 0; c < 4; c++) sf[nt][c] = 0.f;

            #pragma unroll
            for (int ks = 0; ks < 4; ks++) {
                uint32_t bk0[4], bk1[4];
                const uint32_t chsw = (uint32_t)(((2 * ks + cq) ^ r7)) << 4;
                ldsm4(bk0, Ks + (uint32_t)((32 * b + rA) * 128) + chsw);
                ldsm4(bk1, Ks + (uint32_t)((32 * b + 16 + rA) * 128) + chsw);
                mma16816(sf[0], aQ[ks], bk0[0], bk0[2]);
                mma16816(sf[1], aQ[ks], bk0[1], bk0[3]);
                mma16816(sf[2], aQ[ks], bk1[0], bk1[2]);
                mma16816(sf[3], aQ[ks], bk1[1], bk1[3]);
            }

            // ---- mask + online softmax update ----
            const int jb  = i0 - 128 + 32 * b;
            const int ir0 = i_base + (lane >> 2);
            const int ir1 = ir0 + 8;
            float bm0 = -1e30f, bm1 = -1e30f;
            #pragma unroll
            for (int nt = 0; nt < 4; nt++) {
                const int jc = jb + nt * 8 + 2 * (lane & 3);
                #pragma unroll
                for (int c = 0; c < 2; c++) {
                    const int j = jc + c;
                    const float s0 = sf[nt][c] * ATT_SCALE;
                    const float s1 = sf[nt][c + 2] * ATT_SCALE;
                    const bool ok0 = (j >= 0) && (j <= ir0) && (ir0 - j < 128);
                    const bool ok1 = (j >= 0) && (j <= ir1) && (ir1 - j < 128);
                    sf[nt][c]     = ok0 ? s0 : -1e30f;
                    sf[nt][c + 2] = ok1 ? s1 : -1e30f;
                    bm0 = fmaxf(bm0, sf[nt][c]);
                    bm1 = fmaxf(bm1, sf[nt][c + 2]);
                }
            }
            bm0 = fmaxf(bm0, __shfl_xor_sync(0xFFFFFFFFu, bm0, 1));
            bm0 = fmaxf(bm0, __shfl_xor_sync(0xFFFFFFFFu, bm0, 2));
            bm1 = fmaxf(bm1, __shfl_xor_sync(0xFFFFFFFFu, bm1, 1));
            bm1 = fmaxf(bm1, __shfl_xor_sync(0xFFFFFFFFu, bm1, 2));

            const float nm0 = fmaxf(m0, bm0), nm1 = fmaxf(m1, bm1);
            const float sc0 = __expf(m0 - nm0), sc1 = __expf(m1 - nm1);
            m0 = nm0; m1 = nm1;
            l0 *= sc0; l1 *= sc1;
            #pragma unroll
            for (int dn = 0; dn < 8; dn++) {
                ofr[dn][0] *= sc0; ofr[dn][1] *= sc0;
                ofr[dn][2] *= sc1; ofr[dn][3] *= sc1;
            }

            uint32_t P01[4], P23[4];
            #pragma unroll
            for (int nt = 0; nt < 4; nt++) {
                const float p0 = __expf(sf[nt][0] - m0);
                const float p1 = __expf(sf[nt][1] - m0);
                const float p2 = __expf(sf[nt][2] - m1);
                const float p3 = __expf(sf[nt][3] - m1);
                l0 += p0 + p1;  l1 += p2 + p3;
                const __half2 h01 = __floats2half2_rn(p0, p1);
                const __half2 h23 = __floats2half2_rn(p2, p3);
                P01[nt] = *reinterpret_cast<const uint32_t*>(&h01);
                P23[nt] = *reinterpret_cast<const uint32_t*>(&h23);
            }

            // ---- O += P V ----
            #pragma unroll
            for (int kt = 0; kt < 2; kt++) {
                uint32_t aP[4] = {P01[2 * kt], P23[2 * kt],
                                  P01[2 * kt + 1], P23[2 * kt + 1]};
                const int vr = 32 * b + 16 * kt + vrow_l;
                #pragma unroll
                for (int dp = 0; dp < 4; dp++) {
                    uint32_t bv[4];
                    ldsm4t(bv, Vs + (uint32_t)(vr * 128) +
                               ((uint32_t)(((2 * dp + vnsel) ^ (vr & 7))) << 4));
                    mma16816(ofr[2 * dp],     aP, bv[0], bv[2]);
                    mma16816(ofr[2 * dp + 1], aP, bv[1], bv[3]);
                }
            }
        }

        // ---- finalize: denominators (+ sink), normalize, store fp16 ----
        l0 += __shfl_xor_sync(0xFFFFFFFFu, l0, 1);
        l0 += __shfl_xor_sync(0xFFFFFFFFu, l0, 2);
        l1 += __shfl_xor_sync(0xFFFFFFFFu, l1, 1);
        l1 += __shfl_xor_sync(0xFFFFFFFFu, l1, 2);
        l0 += __expf(snk - m0);
        l1 += __expf(snk - m1);
        const float inv0 = 1.f / l0, inv1 = 1.f / l1;

        const int r0 = i_base + (lane >> 2);
        #pragma unroll
        for (int dn = 0; dn < 8; dn++) {
            const int col = h * 64 + dn * 8 + 2 * (lane & 3);
            const __half2 o0 = __floats2half2_rn(ofr[dn][0] * inv0, ofr[dn][1] * inv0);
            const __half2 o1 = __floats2half2_rn(ofr[dn][2] * inv1, ofr[dn][3] * inv1);
            *reinterpret_cast<__half2*>(out_hi + (size_t)r0 * Q_SIZE + col)       = o0;
            *reinterpret_cast<__half2*>(out_hi + (size_t)(r0 + 8) * Q_SIZE + col) = o1;
        }
    }
}

// ---------------------------------------------------------------------------
// Launch
// ---------------------------------------------------------------------------
extern "C" void kernel_launch(void* const* d_in, const int* in_sizes, int n_in,
                              void* d_out, int out_size)
{
    const int*   positions = (const int*)  d_in[0];
    const float* hidden    = (const float*)d_in[1];
    const float* W_qkv     = (const float*)d_in[2];
    const float* b_qkv     = (const float*)d_in[3];
    const float* W_o       = (const float*)d_in[4];
    const float* b_o       = (const float*)d_in[5];
    const float* sinks     = (const float*)d_in[6];
    float* out = (float*)d_out;

    float *qkv;
    __half *h_hi, *wq_hi, *wo_hi, *a_hi;
    cudaGetSymbolAddress((void**)&qkv,   g_qkv);
    cudaGetSymbolAddress((void**)&h_hi,  g_h_hi);
    cudaGetSymbolAddress((void**)&wq_hi, g_wq_hi);
    cudaGetSymbolAddress((void**)&wo_hi, g_wo_hi);
    cudaGetSymbolAddress((void**)&a_hi,  g_a_hi);

    static bool attr_done = false;
    if (!attr_done) {
        cudaFuncSetAttribute(hgemm1_kernel,
                             cudaFuncAttributeMaxDynamicSharedMemorySize, GEMM_DSMEM);
        cudaFuncSetAttribute(attn_mma_kernel,
                             cudaFuncAttributeMaxDynamicSharedMemorySize, ATTN_DSMEM);
        attr_done = true;
    }

    // 0a) hidden -> fp16 hi
    {
        const int n4 = T_LEN * HIDDEN / 4;
        split_hi_kernel<<<(n4 + 255) / 256, 256>>>(hidden, h_hi, n4);
    }
    // 0b) transpose weights (hi only)
    {
        dim3 b(32, 8);
        dim3 g1(QKV_COLS / 32, HIDDEN / 32);
        thi_kernel<<<g1, b>>>(W_qkv, HIDDEN, QKV_COLS, QKV_COLS, wq_hi);
        dim3 g2(O_NPAD / 32, Q_SIZE / 32);
        thi_kernel<<<g2, b>>>(W_o, Q_SIZE, HIDDEN, O_NPAD, wo_hi);
    }
    // 1) QKV projection
    {
        dim3 grid(QKV_COLS / 128, T_LEN / 128);
        hgemm1_kernel<<<grid, 256, GEMM_DSMEM>>>(h_hi, wq_hi,
                                                 b_qkv, qkv, QKV_COLS, HIDDEN);
    }
    // 2) RoPE
    {
        const int total = T_LEN * (N_HEADS + N_KV) * 32;
        rope_kernel<<<(total + 255) / 256, 256>>>(positions, qkv);
    }
    // 3) tensor-core flash attention
    {
        dim3 grid(T_LEN / 64, N_KV);
        attn_mma_kernel<<<grid, 256, ATTN_DSMEM>>>(qkv, sinks, a_hi);
    }
    // 4) O projection
    {
        dim3 grid(O_NPAD / 128, T_LEN / 128);
        hgemm1_kernel<<<grid, 256, GEMM_DSMEM>>>(a_hi, wo_hi,
                                                 b_o, out, HIDDEN, Q_SIZE);
    }
}

// round 10
// speedup vs baseline: 1.8585x; 1.0780x over previous
#include <cuda_runtime.h>
#include <cuda_fp16.h>
#include <cstdint>
#include <cmath>

// ---------------------------------------------------------------------------
// GPT-OSS attention block on sm_100 (legacy mma.sync path).
// Round 10: R9's GEMM (K-chunk 64, GS=3, one sync/chunk, 2 CTAs/SM) with the
// stream fork REVERTED (suspected capture/alloc-guard violation).
// Tensor-core flash attention unchanged from R8.
// ---------------------------------------------------------------------------

#define T_LEN      1536
#define HIDDEN     2880
#define N_HEADS    64
#define N_KV       8
#define HEAD_DIM   64
#define WINDOW     128
#define Q_SIZE     4096
#define KV_SIZE    512
#define QKV_COLS   5120
#define O_NPAD     2944
#define ATT_SCALE  0.125f

// ---------------- scratch ---------------------------------------------------
__device__ __align__(256) float  g_qkv   [(size_t)T_LEN * QKV_COLS];
__device__ __align__(256) __half g_h_hi  [(size_t)T_LEN * HIDDEN];
__device__ __align__(256) __half g_wq_hi [(size_t)QKV_COLS * HIDDEN];   // [N,K]
__device__ __align__(256) __half g_wo_hi [(size_t)O_NPAD * Q_SIZE];     // [N,K]
__device__ __align__(256) __half g_a_hi  [(size_t)T_LEN * Q_SIZE];

// ---------------- helpers ---------------------------------------------------
static __device__ __forceinline__ uint32_t smem_u32(const void* p) {
    uint32_t a;
    asm("{ .reg .u64 t; cvta.to.shared.u64 t, %1; cvt.u32.u64 %0, t; }"
        : "=r"(a) : "l"(p));
    return a;
}

#define CP_ASYNC16(dst, src) \
    asm volatile("cp.async.cg.shared.global [%0], [%1], 16;" :: "r"(dst), "l"(src))
#define CP_COMMIT() asm volatile("cp.async.commit_group;")
#define CP_WAIT1()  asm volatile("cp.async.wait_group 1;")

static __device__ __forceinline__ void ldsm4(uint32_t* r, uint32_t addr) {
    asm volatile("ldmatrix.sync.aligned.m8n8.x4.shared.b16 {%0,%1,%2,%3}, [%4];"
                 : "=r"(r[0]), "=r"(r[1]), "=r"(r[2]), "=r"(r[3]) : "r"(addr));
}

static __device__ __forceinline__ void ldsm4t(uint32_t* r, uint32_t addr) {
    asm volatile("ldmatrix.sync.aligned.m8n8.x4.trans.shared.b16 {%0,%1,%2,%3}, [%4];"
                 : "=r"(r[0]), "=r"(r[1]), "=r"(r[2]), "=r"(r[3]) : "r"(addr));
}

static __device__ __forceinline__ void mma16816(float* d, const uint32_t* a,
                                                uint32_t b0, uint32_t b1) {
    asm volatile("mma.sync.aligned.m16n8k16.row.col.f32.f16.f16.f32 "
                 "{%0,%1,%2,%3}, {%4,%5,%6,%7}, {%8,%9}, {%0,%1,%2,%3};"
                 : "+f"(d[0]), "+f"(d[1]), "+f"(d[2]), "+f"(d[3])
                 : "r"(a[0]), "r"(a[1]), "r"(a[2]), "r"(a[3]), "r"(b0), "r"(b1));
}

// ---------------------------------------------------------------------------
// 1-pass fp16 HMMA GEMM:  C[M,Nreal] = A_hi[M,K] @ B_hi[Npad,K]^T + bias
// CTA 128x128, K-chunk 64, stage = {A 16K, B 16K}, GS=3, 256 threads
// (8 warps of 64x32), 2 CTAs/SM, SW128 swizzle, one sync per chunk.
// ---------------------------------------------------------------------------
#define GS           3
#define TILE_BYTES   16384
#define STAGE_BYTES  (2 * TILE_BYTES)              // 32 KB
#define GEMM_DSMEM   (GS * STAGE_BYTES + 1024)     // 99,328 B -> 2 CTAs/SM

static __device__ __forceinline__ void load_chunk(
    uint32_t st,
    const __half* __restrict__ Ah, const __half* __restrict__ Bh,
    int m0, int n0, int kk, int K, int tid)
{
    #pragma unroll
    for (int i = 0; i < 4; i++) {
        int ch  = tid + (i << 8);            // 0..1023
        int rw  = ch >> 3;                   // row 0..127
        int c16 = ch & 7;                    // 16B chunk in 128B row
        uint32_t off = (uint32_t)(rw << 7) + (uint32_t)(c16 << 4);
        uint32_t sw  = off ^ ((off >> 3) & 0x70);
        const char* sa = (const char*)(Ah + (size_t)(m0 + rw) * K + kk) + (c16 << 4);
        const char* sb = (const char*)(Bh + (size_t)(n0 + rw) * K + kk) + (c16 << 4);
        CP_ASYNC16(st + sw,              sa);
        CP_ASYNC16(st + TILE_BYTES + sw, sb);
    }
}

__global__ __launch_bounds__(256, 2)
void hgemm1_kernel(const __half* __restrict__ A_hi,
                   const __half* __restrict__ B_hi,
                   const float* __restrict__ bias, float* __restrict__ C,
                   int Nreal, int K)
{
    extern __shared__ char dynsmem[];
    const uint32_t tile0 = (smem_u32(dynsmem) + 1023u) & ~1023u;

    const int tid  = threadIdx.x;
    const int wid  = tid >> 5;
    const int lane = tid & 31;
    const int m0   = blockIdx.y * 128;
    const int n0   = blockIdx.x * 128;
    const int wm   = (wid & 1) * 64;
    const int wn   = (wid >> 1) * 32;

    const int r7 = lane & 7;
    const int q  = lane >> 3;
    const int rA = ((q & 1) << 3) + r7;        // ldmatrix row-in-16
    const int cq = q >> 1;                     // k16 quarter selector

    const int nch = K >> 6;

    float acc[4][4][4];
    #pragma unroll
    for (int a = 0; a < 4; a++)
        #pragma unroll
        for (int b = 0; b < 4; b++)
            #pragma unroll
            for (int c = 0; c < 4; c++) acc[a][b][c] = 0.0f;

    // prologue: chunks 0..GS-2
    #pragma unroll
    for (int c = 0; c < GS - 1; c++) {
        load_chunk(tile0 + c * STAGE_BYTES, A_hi, B_hi, m0, n0, c << 6, K, tid);
        CP_COMMIT();
    }

    int stage_c = 0, stage_p = GS - 1;
    for (int c = 0; c < nch; c++) {
        CP_WAIT1();                 // groups <= c complete (commit count aligned)
        __syncthreads();            // also orders stage reuse across warps

        if (c + GS - 1 < nch)
            load_chunk(tile0 + stage_p * STAGE_BYTES, A_hi, B_hi,
                       m0, n0, (c + GS - 1) << 6, K, tid);
        CP_COMMIT();                // unconditional: keeps group counting uniform
        if (++stage_p == GS) stage_p = 0;

        const uint32_t aB = tile0 + stage_c * STAGE_BYTES;
        const uint32_t bB = aB + TILE_BYTES;
        if (++stage_c == GS) stage_c = 0;

        #pragma unroll
        for (int ks = 0; ks < 4; ks++) {
            uint32_t afr[4][4], bfr[2][4];
            const uint32_t chsw = (uint32_t)(((ks * 2 + cq) ^ r7) << 4);
            #pragma unroll
            for (int mt = 0; mt < 4; mt++)
                ldsm4(afr[mt], aB + (uint32_t)((wm + mt * 16 + rA) << 7) + chsw);
            #pragma unroll
            for (int ng = 0; ng < 2; ng++)
                ldsm4(bfr[ng], bB + (uint32_t)((wn + ng * 16 + rA) << 7) + chsw);

            #pragma unroll
            for (int mt = 0; mt < 4; mt++)
                #pragma unroll
                for (int nt = 0; nt < 4; nt++) {
                    const int ng = nt >> 1, hl = nt & 1;
                    mma16816(acc[mt][nt], afr[mt], bfr[ng][hl], bfr[ng][hl + 2]);
                }
        }
    }

    // epilogue
    const int trow = lane >> 2;
    const int tcol = (lane & 3) * 2;
    #pragma unroll
    for (int mt = 0; mt < 4; mt++) {
        #pragma unroll
        for (int nt = 0; nt < 4; nt++) {
            const int col = n0 + wn + nt * 8 + tcol;
            if (col < Nreal) {
                const float2 b2 = *reinterpret_cast<const float2*>(bias + col);
                const int row0 = m0 + wm + mt * 16 + trow;
                float2 o0, o1;
                o0.x = acc[mt][nt][0] + b2.x;  o0.y = acc[mt][nt][1] + b2.y;
                o1.x = acc[mt][nt][2] + b2.x;  o1.y = acc[mt][nt][3] + b2.y;
                *reinterpret_cast<float2*>(C + (size_t)row0 * Nreal + col)       = o0;
                *reinterpret_cast<float2*>(C + (size_t)(row0 + 8) * Nreal + col) = o1;
            }
        }
    }
}

// ---------------------------------------------------------------------------
// fp32 -> fp16 (hi only)
// ---------------------------------------------------------------------------
__global__ void split_hi_kernel(const float* __restrict__ in,
                                __half* __restrict__ hi, int n4)
{
    int i = blockIdx.x * blockDim.x + threadIdx.x;
    if (i >= n4) return;
    float4 v = reinterpret_cast<const float4*>(in)[i];
    reinterpret_cast<__half2*>(hi)[2 * i + 0] =
        __halves2half2(__float2half_rn(v.x), __float2half_rn(v.y));
    reinterpret_cast<__half2*>(hi)[2 * i + 1] =
        __halves2half2(__float2half_rn(v.z), __float2half_rn(v.w));
}

// ---------------------------------------------------------------------------
// Transpose: W [K,N] fp32 -> hi fp16 [Npad,K]
// ---------------------------------------------------------------------------
__global__ void thi_kernel(const float* __restrict__ W, int K, int N, int Npad,
                           __half* __restrict__ hi)
{
    __shared__ float tile[32][33];
    const int n0 = blockIdx.x * 32;
    const int k0 = blockIdx.y * 32;
    const int tx = threadIdx.x, ty = threadIdx.y;

    #pragma unroll
    for (int r = ty; r < 32; r += 8) {
        int n = n0 + tx, k = k0 + r;
        tile[r][tx] = (n < N) ? W[(size_t)k * N + n] : 0.0f;
    }
    __syncthreads();
    #pragma unroll
    for (int r = ty; r < 32; r += 8) {
        int n = n0 + r, k = k0 + tx;
        hi[(size_t)n * K + k] = __float2half_rn(tile[tx][r]);
    }
}

// ---------------------------------------------------------------------------
// YaRN RoPE in-place on fp32 qkv
// ---------------------------------------------------------------------------
__global__ void rope_kernel(const int* __restrict__ positions,
                            float* __restrict__ qkv)
{
    const int idx = blockIdx.x * blockDim.x + threadIdx.x;
    const int total = T_LEN * (N_HEADS + N_KV) * 32;
    if (idx >= total) return;

    const int d    = idx & 31;
    const int head = (idx >> 5) % (N_HEADS + N_KV);
    const int t    = idx / (32 * (N_HEADS + N_KV));

    const float p = (float)positions[t];
    const float lnB   = logf(150000.0f);
    const float freq  = expf(lnB * ((float)d / 32.0f));
    const float conc  = 0.1f * logf(32.0f) + 1.0f;
    const float twoPi = 6.283185307179586f;
    const float low   = 32.0f * logf(4096.0f / (32.0f * twoPi)) / lnB;
    const float high  = 32.0f * logf(4096.0f / (1.0f  * twoPi)) / lnB;
    float ramp = ((float)d - low) / (high - low);
    ramp = fminf(fmaxf(ramp, 0.0f), 1.0f);
    const float inv_freq = ramp / (32.0f * freq) + (1.0f - ramp) / freq;

    const float ang = p * inv_freq;
    const float c = cosf(ang) * conc;
    const float s = sinf(ang) * conc;

    float* base = qkv + (size_t)t * QKV_COLS + head * HEAD_DIM;
    const float x1 = base[d];
    const float x2 = base[d + 32];
    base[d]      = x1 * c - x2 * s;
    base[d + 32] = x2 * c + x1 * s;
}

// ---------------------------------------------------------------------------
// Tensor-core flash attention with sink (unchanged from R8).
// ---------------------------------------------------------------------------
#define AROWS       192
#define ATTN_DSMEM  65536

__global__ __launch_bounds__(256, 2)
void attn_mma_kernel(const float* __restrict__ qkv,
                     const float* __restrict__ sinks,
                     __half* __restrict__ out_hi)
{
    extern __shared__ char asmem[];
    const uint32_t sbase = smem_u32(asmem);
    const uint32_t Ks = sbase;
    const uint32_t Vs = sbase + 24576;

    const int tid  = threadIdx.x;
    const int warp = tid >> 5;
    const int lane = tid & 31;
    const int i0   = blockIdx.x * 64;
    const int kv   = blockIdx.y;
    const int h    = kv * 8 + warp;
    const uint32_t Qs = sbase + 49152 + warp * 2048;

    for (int idx = tid; idx < AROWS * 32; idx += 256) {
        const int r = idx >> 5, d2 = idx & 31;
        const int j = i0 - 128 + r;
        float2 kf = make_float2(0.f, 0.f), vf = make_float2(0.f, 0.f);
        if (j >= 0) {
            const float* src = qkv + (size_t)j * QKV_COLS + Q_SIZE + kv * 64 + 2 * d2;
            kf = *reinterpret_cast<const float2*>(src);
            vf = *reinterpret_cast<const float2*>(src + KV_SIZE);
        }
        const uint32_t sw = (uint32_t)(r * 128) +
                            ((uint32_t)((d2 >> 2) ^ (r & 7)) << 4) + (d2 & 3) * 4;
        *reinterpret_cast<__half2*>(asmem + sw)         = __floats2half2_rn(kf.x, kf.y);
        *reinterpret_cast<__half2*>(asmem + 24576 + sw) = __floats2half2_rn(vf.x, vf.y);
    }
    __syncthreads();

    const float snk = sinks[h];
    const int r7 = lane & 7;
    const int qq = lane >> 3;
    const int rA = ((qq & 1) << 3) + r7;
    const int cq = qq >> 1;
    const int vrow_l = (lane & 7) + ((lane >> 4) << 3);
    const int vnsel  = (lane >> 3) & 1;

    for (int mt = 0; mt < 4; mt++) {
        const int i_base = i0 + mt * 16;

        __syncwarp();
        for (int e = lane; e < 512; e += 32) {
            const int r = e >> 5, d2 = e & 31;
            const float2 qf = *reinterpret_cast<const float2*>(
                qkv + (size_t)(i_base + r) * QKV_COLS + h * 64 + 2 * d2);
            const uint32_t sw = (uint32_t)(r * 128) +
                                ((uint32_t)((d2 >> 2) ^ (r & 7)) << 4) + (d2 & 3) * 4;
            *reinterpret_cast<__half2*>(asmem + 49152 + warp * 2048 + sw) =
                __floats2half2_rn(qf.x, qf.y);
        }
        __syncwarp();

        uint32_t aQ[4][4];
        #pragma unroll
        for (int ks = 0; ks < 4; ks++)
            ldsm4(aQ[ks], Qs + (uint32_t)(rA * 128) +
                          ((uint32_t)(((2 * ks + cq) ^ r7)) << 4));

        float m0 = snk, m1 = snk, l0 = 0.f, l1 = 0.f;
        float ofr[8][4];
        #pragma unroll
        for (int dn = 0; dn < 8; dn++)
            #pragma unroll
            for (int c = 0; c < 4; c++) ofr[dn][c] = 0.f;

        const int b_lo = (mt >= 2) ? 1 : 0;
        for (int bb = 0; bb < 5; bb++) {
            const int b = b_lo + bb;

            float sf[4][4];
            #pragma unroll
            for (int nt = 0; nt < 4; nt++)
                #pragma unroll
                for (int c = 0; c < 4; c++) sf[nt][c] = 0.f;

            #pragma unroll
            for (int ks = 0; ks < 4; ks++) {
                uint32_t bk0[4], bk1[4];
                const uint32_t chsw = (uint32_t)(((2 * ks + cq) ^ r7)) << 4;
                ldsm4(bk0, Ks + (uint32_t)((32 * b + rA) * 128) + chsw);
                ldsm4(bk1, Ks + (uint32_t)((32 * b + 16 + rA) * 128) + chsw);
                mma16816(sf[0], aQ[ks], bk0[0], bk0[2]);
                mma16816(sf[1], aQ[ks], bk0[1], bk0[3]);
                mma16816(sf[2], aQ[ks], bk1[0], bk1[2]);
                mma16816(sf[3], aQ[ks], bk1[1], bk1[3]);
            }

            const int jb  = i0 - 128 + 32 * b;
            const int ir0 = i_base + (lane >> 2);
            const int ir1 = ir0 + 8;
            float bm0 = -1e30f, bm1 = -1e30f;
            #pragma unroll
            for (int nt = 0; nt < 4; nt++) {
                const int jc = jb + nt * 8 + 2 * (lane & 3);
                #pragma unroll
                for (int c = 0; c < 2; c++) {
                    const int j = jc + c;
                    const float s0 = sf[nt][c] * ATT_SCALE;
                    const float s1 = sf[nt][c + 2] * ATT_SCALE;
                    const bool ok0 = (j >= 0) && (j <= ir0) && (ir0 - j < 128);
                    const bool ok1 = (j >= 0) && (j <= ir1) && (ir1 - j < 128);
                    sf[nt][c]     = ok0 ? s0 : -1e30f;
                    sf[nt][c + 2] = ok1 ? s1 : -1e30f;
                    bm0 = fmaxf(bm0, sf[nt][c]);
                    bm1 = fmaxf(bm1, sf[nt][c + 2]);
                }
            }
            bm0 = fmaxf(bm0, __shfl_xor_sync(0xFFFFFFFFu, bm0, 1));
            bm0 = fmaxf(bm0, __shfl_xor_sync(0xFFFFFFFFu, bm0, 2));
            bm1 = fmaxf(bm1, __shfl_xor_sync(0xFFFFFFFFu, bm1, 1));
            bm1 = fmaxf(bm1, __shfl_xor_sync(0xFFFFFFFFu, bm1, 2));

            const float nm0 = fmaxf(m0, bm0), nm1 = fmaxf(m1, bm1);
            const float sc0 = __expf(m0 - nm0), sc1 = __expf(m1 - nm1);
            m0 = nm0; m1 = nm1;
            l0 *= sc0; l1 *= sc1;
            #pragma unroll
            for (int dn = 0; dn < 8; dn++) {
                ofr[dn][0] *= sc0; ofr[dn][1] *= sc0;
                ofr[dn][2] *= sc1; ofr[dn][3] *= sc1;
            }

            uint32_t P01[4], P23[4];
            #pragma unroll
            for (int nt = 0; nt < 4; nt++) {
                const float p0 = __expf(sf[nt][0] - m0);
                const float p1 = __expf(sf[nt][1] - m0);
                const float p2 = __expf(sf[nt][2] - m1);
                const float p3 = __expf(sf[nt][3] - m1);
                l0 += p0 + p1;  l1 += p2 + p3;
                const __half2 h01 = __floats2half2_rn(p0, p1);
                const __half2 h23 = __floats2half2_rn(p2, p3);
                P01[nt] = *reinterpret_cast<const uint32_t*>(&h01);
                P23[nt] = *reinterpret_cast<const uint32_t*>(&h23);
            }

            #pragma unroll
            for (int kt = 0; kt < 2; kt++) {
                uint32_t aP[4] = {P01[2 * kt], P23[2 * kt],
                                  P01[2 * kt + 1], P23[2 * kt + 1]};
                const int vr = 32 * b + 16 * kt + vrow_l;
                #pragma unroll
                for (int dp = 0; dp < 4; dp++) {
                    uint32_t bv[4];
                    ldsm4t(bv, Vs + (uint32_t)(vr * 128) +
                               ((uint32_t)(((2 * dp + vnsel) ^ (vr & 7))) << 4));
                    mma16816(ofr[2 * dp],     aP, bv[0], bv[2]);
                    mma16816(ofr[2 * dp + 1], aP, bv[1], bv[3]);
                }
            }
        }

        l0 += __shfl_xor_sync(0xFFFFFFFFu, l0, 1);
        l0 += __shfl_xor_sync(0xFFFFFFFFu, l0, 2);
        l1 += __shfl_xor_sync(0xFFFFFFFFu, l1, 1);
        l1 += __shfl_xor_sync(0xFFFFFFFFu, l1, 2);
        l0 += __expf(snk - m0);
        l1 += __expf(snk - m1);
        const float inv0 = 1.f / l0, inv1 = 1.f / l1;

        const int r0 = i_base + (lane >> 2);
        #pragma unroll
        for (int dn = 0; dn < 8; dn++) {
            const int col = h * 64 + dn * 8 + 2 * (lane & 3);
            const __half2 o0 = __floats2half2_rn(ofr[dn][0] * inv0, ofr[dn][1] * inv0);
            const __half2 o1 = __floats2half2_rn(ofr[dn][2] * inv1, ofr[dn][3] * inv1);
            *reinterpret_cast<__half2*>(out_hi + (size_t)r0 * Q_SIZE + col)       = o0;
            *reinterpret_cast<__half2*>(out_hi + (size_t)(r0 + 8) * Q_SIZE + col) = o1;
        }
    }
}

// ---------------------------------------------------------------------------
// Launch — plain serial chain on the default stream (no streams, no events).
// ---------------------------------------------------------------------------
extern "C" void kernel_launch(void* const* d_in, const int* in_sizes, int n_in,
                              void* d_out, int out_size)
{
    const int*   positions = (const int*)  d_in[0];
    const float* hidden    = (const float*)d_in[1];
    const float* W_qkv     = (const float*)d_in[2];
    const float* b_qkv     = (const float*)d_in[3];
    const float* W_o       = (const float*)d_in[4];
    const float* b_o       = (const float*)d_in[5];
    const float* sinks     = (const float*)d_in[6];
    float* out = (float*)d_out;

    float *qkv;
    __half *h_hi, *wq_hi, *wo_hi, *a_hi;
    cudaGetSymbolAddress((void**)&qkv,   g_qkv);
    cudaGetSymbolAddress((void**)&h_hi,  g_h_hi);
    cudaGetSymbolAddress((void**)&wq_hi, g_wq_hi);
    cudaGetSymbolAddress((void**)&wo_hi, g_wo_hi);
    cudaGetSymbolAddress((void**)&a_hi,  g_a_hi);

    static bool attr_done = false;
    if (!attr_done) {
        cudaFuncSetAttribute(hgemm1_kernel,
                             cudaFuncAttributeMaxDynamicSharedMemorySize, GEMM_DSMEM);
        cudaFuncSetAttribute(attn_mma_kernel,
                             cudaFuncAttributeMaxDynamicSharedMemorySize, ATTN_DSMEM);
        attr_done = true;
    }

    // 0a) hidden -> fp16 hi
    {
        const int n4 = T_LEN * HIDDEN / 4;
        split_hi_kernel<<<(n4 + 255) / 256, 256>>>(hidden, h_hi, n4);
    }
    // 0b) transpose weights (hi only)
    {
        dim3 b(32, 8);
        dim3 g1(QKV_COLS / 32, HIDDEN / 32);
        thi_kernel<<<g1, b>>>(W_qkv, HIDDEN, QKV_COLS, QKV_COLS, wq_hi);
        dim3 g2(O_NPAD / 32, Q_SIZE / 32);
        thi_kernel<<<g2, b>>>(W_o, Q_SIZE, HIDDEN, O_NPAD, wo_hi);
    }
    // 1) QKV projection
    {
        dim3 grid(QKV_COLS / 128, T_LEN / 128);
        hgemm1_kernel<<<grid, 256, GEMM_DSMEM>>>(h_hi, wq_hi,
                                                 b_qkv, qkv, QKV_COLS, HIDDEN);
    }
    // 2) RoPE
    {
        const int total = T_LEN * (N_HEADS + N_KV) * 32;
        rope_kernel<<<(total + 255) / 256, 256>>>(positions, qkv);
    }
    // 3) tensor-core flash attention
    {
        dim3 grid(T_LEN / 64, N_KV);
        attn_mma_kernel<<<grid, 256, ATTN_DSMEM>>>(qkv, sinks, a_hi);
    }
    // 4) O projection
    {
        dim3 grid(O_NPAD / 128, T_LEN / 128);
        hgemm1_kernel<<<grid, 256, GEMM_DSMEM>>>(a_hi, wo_hi,
                                                 b_o, out, HIDDEN, Q_SIZE);
    }
}

// round 11
// speedup vs baseline: 2.1270x; 1.1445x over previous
#include <cuda_runtime.h>
#include <cuda_fp16.h>
#include <cstdint>
#include <cmath>

// ---------------------------------------------------------------------------
// GPT-OSS attention block on sm_100 (legacy mma.sync path).
// Round 11: single fused preprocessing kernel (fp32->fp16 hidden, both weight
// transposes, RoPE cos/sin table); rope kernel removed — attention applies
// RoPE from the table during K/Q smem staging (numerically identical).
// GEMMs and attention core unchanged from R10.
// ---------------------------------------------------------------------------

#define T_LEN      1536
#define HIDDEN     2880
#define N_HEADS    64
#define N_KV       8
#define HEAD_DIM   64
#define WINDOW     128
#define Q_SIZE     4096
#define KV_SIZE    512
#define QKV_COLS   5120
#define O_NPAD     2944
#define ATT_SCALE  0.125f

// ---------------- scratch ---------------------------------------------------
__device__ __align__(256) float  g_qkv  [(size_t)T_LEN * QKV_COLS];
__device__ __align__(256) __half g_h_hi [(size_t)T_LEN * HIDDEN];
__device__ __align__(256) __half g_wq_hi[(size_t)QKV_COLS * HIDDEN];   // [N,K]
__device__ __align__(256) __half g_wo_hi[(size_t)O_NPAD * Q_SIZE];     // [N,K]
__device__ __align__(256) __half g_a_hi [(size_t)T_LEN * Q_SIZE];
__device__ __align__(256) float  g_rcos [(size_t)T_LEN * 32];          // cos*conc
__device__ __align__(256) float  g_rsin [(size_t)T_LEN * 32];          // sin*conc

// ---------------- helpers ---------------------------------------------------
static __device__ __forceinline__ uint32_t smem_u32(const void* p) {
    uint32_t a;
    asm("{ .reg .u64 t; cvta.to.shared.u64 t, %1; cvt.u32.u64 %0, t; }"
        : "=r"(a) : "l"(p));
    return a;
}

#define CP_ASYNC16(dst, src) \
    asm volatile("cp.async.cg.shared.global [%0], [%1], 16;" :: "r"(dst), "l"(src))
#define CP_COMMIT() asm volatile("cp.async.commit_group;")
#define CP_WAIT1()  asm volatile("cp.async.wait_group 1;")

static __device__ __forceinline__ void ldsm4(uint32_t* r, uint32_t addr) {
    asm volatile("ldmatrix.sync.aligned.m8n8.x4.shared.b16 {%0,%1,%2,%3}, [%4];"
                 : "=r"(r[0]), "=r"(r[1]), "=r"(r[2]), "=r"(r[3]) : "r"(addr));
}

static __device__ __forceinline__ void ldsm4t(uint32_t* r, uint32_t addr) {
    asm volatile("ldmatrix.sync.aligned.m8n8.x4.trans.shared.b16 {%0,%1,%2,%3}, [%4];"
                 : "=r"(r[0]), "=r"(r[1]), "=r"(r[2]), "=r"(r[3]) : "r"(addr));
}

static __device__ __forceinline__ void mma16816(float* d, const uint32_t* a,
                                                uint32_t b0, uint32_t b1) {
    asm volatile("mma.sync.aligned.m16n8k16.row.col.f32.f16.f16.f32 "
                 "{%0,%1,%2,%3}, {%4,%5,%6,%7}, {%8,%9}, {%0,%1,%2,%3};"
                 : "+f"(d[0]), "+f"(d[1]), "+f"(d[2]), "+f"(d[3])
                 : "r"(a[0]), "r"(a[1]), "r"(a[2]), "r"(a[3]), "r"(b0), "r"(b1));
}

// ---------------------------------------------------------------------------
// 1-pass fp16 HMMA GEMM (unchanged from R10)
// ---------------------------------------------------------------------------
#define GS           3
#define TILE_BYTES   16384
#define STAGE_BYTES  (2 * TILE_BYTES)
#define GEMM_DSMEM   (GS * STAGE_BYTES + 1024)

static __device__ __forceinline__ void load_chunk(
    uint32_t st,
    const __half* __restrict__ Ah, const __half* __restrict__ Bh,
    int m0, int n0, int kk, int K, int tid)
{
    #pragma unroll
    for (int i = 0; i < 4; i++) {
        int ch  = tid + (i << 8);
        int rw  = ch >> 3;
        int c16 = ch & 7;
        uint32_t off = (uint32_t)(rw << 7) + (uint32_t)(c16 << 4);
        uint32_t sw  = off ^ ((off >> 3) & 0x70);
        const char* sa = (const char*)(Ah + (size_t)(m0 + rw) * K + kk) + (c16 << 4);
        const char* sb = (const char*)(Bh + (size_t)(n0 + rw) * K + kk) + (c16 << 4);
        CP_ASYNC16(st + sw,              sa);
        CP_ASYNC16(st + TILE_BYTES + sw, sb);
    }
}

__global__ __launch_bounds__(256, 2)
void hgemm1_kernel(const __half* __restrict__ A_hi,
                   const __half* __restrict__ B_hi,
                   const float* __restrict__ bias, float* __restrict__ C,
                   int Nreal, int K)
{
    extern __shared__ char dynsmem[];
    const uint32_t tile0 = (smem_u32(dynsmem) + 1023u) & ~1023u;

    const int tid  = threadIdx.x;
    const int wid  = tid >> 5;
    const int lane = tid & 31;
    const int m0   = blockIdx.y * 128;
    const int n0   = blockIdx.x * 128;
    const int wm   = (wid & 1) * 64;
    const int wn   = (wid >> 1) * 32;

    const int r7 = lane & 7;
    const int q  = lane >> 3;
    const int rA = ((q & 1) << 3) + r7;
    const int cq = q >> 1;

    const int nch = K >> 6;

    float acc[4][4][4];
    #pragma unroll
    for (int a = 0; a < 4; a++)
        #pragma unroll
        for (int b = 0; b < 4; b++)
            #pragma unroll
            for (int c = 0; c < 4; c++) acc[a][b][c] = 0.0f;

    #pragma unroll
    for (int c = 0; c < GS - 1; c++) {
        load_chunk(tile0 + c * STAGE_BYTES, A_hi, B_hi, m0, n0, c << 6, K, tid);
        CP_COMMIT();
    }

    int stage_c = 0, stage_p = GS - 1;
    for (int c = 0; c < nch; c++) {
        CP_WAIT1();
        __syncthreads();

        if (c + GS - 1 < nch)
            load_chunk(tile0 + stage_p * STAGE_BYTES, A_hi, B_hi,
                       m0, n0, (c + GS - 1) << 6, K, tid);
        CP_COMMIT();
        if (++stage_p == GS) stage_p = 0;

        const uint32_t aB = tile0 + stage_c * STAGE_BYTES;
        const uint32_t bB = aB + TILE_BYTES;
        if (++stage_c == GS) stage_c = 0;

        #pragma unroll
        for (int ks = 0; ks < 4; ks++) {
            uint32_t afr[4][4], bfr[2][4];
            const uint32_t chsw = (uint32_t)(((ks * 2 + cq) ^ r7) << 4);
            #pragma unroll
            for (int mt = 0; mt < 4; mt++)
                ldsm4(afr[mt], aB + (uint32_t)((wm + mt * 16 + rA) << 7) + chsw);
            #pragma unroll
            for (int ng = 0; ng < 2; ng++)
                ldsm4(bfr[ng], bB + (uint32_t)((wn + ng * 16 + rA) << 7) + chsw);

            #pragma unroll
            for (int mt = 0; mt < 4; mt++)
                #pragma unroll
                for (int nt = 0; nt < 4; nt++) {
                    const int ng = nt >> 1, hl = nt & 1;
                    mma16816(acc[mt][nt], afr[mt], bfr[ng][hl], bfr[ng][hl + 2]);
                }
        }
    }

    const int trow = lane >> 2;
    const int tcol = (lane & 3) * 2;
    #pragma unroll
    for (int mt = 0; mt < 4; mt++) {
        #pragma unroll
        for (int nt = 0; nt < 4; nt++) {
            const int col = n0 + wn + nt * 8 + tcol;
            if (col < Nreal) {
                const float2 b2 = *reinterpret_cast<const float2*>(bias + col);
                const int row0 = m0 + wm + mt * 16 + trow;
                float2 o0, o1;
                o0.x = acc[mt][nt][0] + b2.x;  o0.y = acc[mt][nt][1] + b2.y;
                o1.x = acc[mt][nt][2] + b2.x;  o1.y = acc[mt][nt][3] + b2.y;
                *reinterpret_cast<float2*>(C + (size_t)row0 * Nreal + col)       = o0;
                *reinterpret_cast<float2*>(C + (size_t)(row0 + 8) * Nreal + col) = o1;
            }
        }
    }
}

// ---------------------------------------------------------------------------
// Fused preprocessing: 4 independent jobs by block range.
//   job0: hidden fp32 -> fp16                  (4320 blocks)
//   job1: W_qkv [K,N] -> wq_hi [N,K] fp16      (14400 blocks)
//   job2: W_o   [K,N] -> wo_hi [Npad,K] fp16   (11776 blocks)
//   job3: RoPE cos/sin*conc table [T,32]       (192 blocks)
// ---------------------------------------------------------------------------
#define PP_SPLIT_BLOCKS  4320
#define PP_THI1_BLOCKS   14400   // (5120/32) x (2880/32)
#define PP_THI2_BLOCKS   11776   // (2944/32) x (4096/32)
#define PP_ROPE_BLOCKS   192
#define PP_TOTAL_BLOCKS  (PP_SPLIT_BLOCKS + PP_THI1_BLOCKS + PP_THI2_BLOCKS + PP_ROPE_BLOCKS)

__global__ __launch_bounds__(256)
void preproc_kernel(const float* __restrict__ hidden,
                    const float* __restrict__ W_qkv,
                    const float* __restrict__ W_o,
                    const int* __restrict__ positions,
                    __half* __restrict__ h_hi,
                    __half* __restrict__ wq_hi,
                    __half* __restrict__ wo_hi,
                    float* __restrict__ rcos,
                    float* __restrict__ rsin)
{
    __shared__ float tile[32][33];
    const int bid = blockIdx.x;
    const int tid = threadIdx.x;

    if (bid < PP_SPLIT_BLOCKS) {
        // job0: hidden -> fp16
        const int i = bid * 256 + tid;           // float4 index, exact fit
        float4 v = reinterpret_cast<const float4*>(hidden)[i];
        reinterpret_cast<__half2*>(h_hi)[2 * i + 0] =
            __halves2half2(__float2half_rn(v.x), __float2half_rn(v.y));
        reinterpret_cast<__half2*>(h_hi)[2 * i + 1] =
            __halves2half2(__float2half_rn(v.z), __float2half_rn(v.w));
        return;
    }

    if (bid < PP_SPLIT_BLOCKS + PP_THI1_BLOCKS + PP_THI2_BLOCKS) {
        // job1/job2: transpose + convert weights
        const bool j1 = bid < PP_SPLIT_BLOCKS + PP_THI1_BLOCKS;
        const int  b  = j1 ? (bid - PP_SPLIT_BLOCKS)
                           : (bid - PP_SPLIT_BLOCKS - PP_THI1_BLOCKS);
        const int  nx = j1 ? (QKV_COLS / 32) : (O_NPAD / 32);
        const int  K  = j1 ? HIDDEN : Q_SIZE;
        const int  N  = j1 ? QKV_COLS : HIDDEN;
        const float* __restrict__ W = j1 ? W_qkv : W_o;
        __half* __restrict__ dst    = j1 ? wq_hi : wo_hi;

        const int n0 = (b % nx) * 32;
        const int k0 = (b / nx) * 32;
        const int tx = tid & 31, ty = tid >> 5;

        #pragma unroll
        for (int r = ty; r < 32; r += 8) {
            int n = n0 + tx, k = k0 + r;
            tile[r][tx] = (n < N) ? W[(size_t)k * N + n] : 0.0f;
        }
        __syncthreads();
        #pragma unroll
        for (int r = ty; r < 32; r += 8) {
            int n = n0 + r, k = k0 + tx;
            dst[(size_t)n * K + k] = __float2half_rn(tile[tx][r]);
        }
        return;
    }

    // job3: RoPE table  (t, d) -> cos*conc, sin*conc
    {
        const int i = (bid - PP_SPLIT_BLOCKS - PP_THI1_BLOCKS - PP_THI2_BLOCKS) * 256 + tid;
        if (i >= T_LEN * 32) return;
        const int d = i & 31;
        const int t = i >> 5;

        const float p = (float)positions[t];
        const float lnB   = logf(150000.0f);
        const float freq  = expf(lnB * ((float)d / 32.0f));
        const float conc  = 0.1f * logf(32.0f) + 1.0f;
        const float twoPi = 6.283185307179586f;
        const float low   = 32.0f * logf(4096.0f / (32.0f * twoPi)) / lnB;
        const float high  = 32.0f * logf(4096.0f / (1.0f  * twoPi)) / lnB;
        float ramp = ((float)d - low) / (high - low);
        ramp = fminf(fmaxf(ramp, 0.0f), 1.0f);
        const float inv_freq = ramp / (32.0f * freq) + (1.0f - ramp) / freq;

        const float ang = p * inv_freq;
        rcos[i] = cosf(ang) * conc;
        rsin[i] = sinf(ang) * conc;
    }
}

// ---------------------------------------------------------------------------
// Tensor-core flash attention with sink; RoPE applied from table during
// K/Q staging (fp32 rotation then fp16 convert — identical numerics to the
// old separate rope kernel).
// ---------------------------------------------------------------------------
#define AROWS       192
#define ATTN_DSMEM  65536

__global__ __launch_bounds__(256, 2)
void attn_mma_kernel(const float* __restrict__ qkv,
                     const float* __restrict__ sinks,
                     const float* __restrict__ rcos,
                     const float* __restrict__ rsin,
                     __half* __restrict__ out_hi)
{
    extern __shared__ char asmem[];
    const uint32_t sbase = smem_u32(asmem);
    const uint32_t Ks = sbase;
    const uint32_t Vs = sbase + 24576;

    const int tid  = threadIdx.x;
    const int warp = tid >> 5;
    const int lane = tid & 31;
    const int i0   = blockIdx.x * 64;
    const int kv   = blockIdx.y;
    const int h    = kv * 8 + warp;
    const uint32_t Qs = sbase + 49152 + warp * 2048;

    // ---- stage K rows with RoPE (pairs d, d+32), fp16 swizzled ----
    for (int idx = tid; idx < AROWS * 16; idx += 256) {
        const int r = idx >> 4, d2 = idx & 15;   // dims 2d2,2d2+1 (+32 partners)
        const int j = i0 - 128 + r;
        float2 y1 = make_float2(0.f, 0.f), y2 = make_float2(0.f, 0.f);
        if (j >= 0) {
            const float* src = qkv + (size_t)j * QKV_COLS + Q_SIZE + kv * 64;
            const float2 x1 = *reinterpret_cast<const float2*>(src + 2 * d2);
            const float2 x2 = *reinterpret_cast<const float2*>(src + 2 * d2 + 32);
            const float2 cc = *reinterpret_cast<const float2*>(rcos + j * 32 + 2 * d2);
            const float2 ss = *reinterpret_cast<const float2*>(rsin + j * 32 + 2 * d2);
            y1.x = x1.x * cc.x - x2.x * ss.x;  y1.y = x1.y * cc.y - x2.y * ss.y;
            y2.x = x2.x * cc.x + x1.x * ss.x;  y2.y = x2.y * cc.y + x1.y * ss.y;
        }
        const int d2b = d2 + 16;
        const uint32_t sw1 = (uint32_t)(r * 128) +
                             ((uint32_t)((d2 >> 2) ^ (r & 7)) << 4) + (d2 & 3) * 4;
        const uint32_t sw2 = (uint32_t)(r * 128) +
                             ((uint32_t)((d2b >> 2) ^ (r & 7)) << 4) + (d2b & 3) * 4;
        *reinterpret_cast<__half2*>(asmem + sw1) = __floats2half2_rn(y1.x, y1.y);
        *reinterpret_cast<__half2*>(asmem + sw2) = __floats2half2_rn(y2.x, y2.y);
    }
    // ---- stage V rows (no RoPE) ----
    for (int idx = tid; idx < AROWS * 32; idx += 256) {
        const int r = idx >> 5, d2 = idx & 31;
        const int j = i0 - 128 + r;
        float2 vf = make_float2(0.f, 0.f);
        if (j >= 0)
            vf = *reinterpret_cast<const float2*>(
                qkv + (size_t)j * QKV_COLS + Q_SIZE + KV_SIZE + kv * 64 + 2 * d2);
        const uint32_t sw = (uint32_t)(r * 128) +
                            ((uint32_t)((d2 >> 2) ^ (r & 7)) << 4) + (d2 & 3) * 4;
        *reinterpret_cast<__half2*>(asmem + 24576 + sw) = __floats2half2_rn(vf.x, vf.y);
    }
    __syncthreads();

    const float snk = sinks[h];
    const int r7 = lane & 7;
    const int qq = lane >> 3;
    const int rA = ((qq & 1) << 3) + r7;
    const int cq = qq >> 1;
    const int vrow_l = (lane & 7) + ((lane >> 4) << 3);
    const int vnsel  = (lane >> 3) & 1;

    for (int mt = 0; mt < 4; mt++) {
        const int i_base = i0 + mt * 16;

        // stage this task's Q tile [16][64] with RoPE, fp16 swizzled
        __syncwarp();
        for (int e = lane; e < 256; e += 32) {
            const int r = e >> 4, d2 = e & 15;
            const int t = i_base + r;
            const float* src = qkv + (size_t)t * QKV_COLS + h * 64;
            const float2 x1 = *reinterpret_cast<const float2*>(src + 2 * d2);
            const float2 x2 = *reinterpret_cast<const float2*>(src + 2 * d2 + 32);
            const float2 cc = *reinterpret_cast<const float2*>(rcos + t * 32 + 2 * d2);
            const float2 ss = *reinterpret_cast<const float2*>(rsin + t * 32 + 2 * d2);
            float2 y1, y2;
            y1.x = x1.x * cc.x - x2.x * ss.x;  y1.y = x1.y * cc.y - x2.y * ss.y;
            y2.x = x2.x * cc.x + x1.x * ss.x;  y2.y = x2.y * cc.y + x1.y * ss.y;
            const int d2b = d2 + 16;
            const uint32_t sw1 = (uint32_t)(r * 128) +
                                 ((uint32_t)((d2 >> 2) ^ (r & 7)) << 4) + (d2 & 3) * 4;
            const uint32_t sw2 = (uint32_t)(r * 128) +
                                 ((uint32_t)((d2b >> 2) ^ (r & 7)) << 4) + (d2b & 3) * 4;
            *reinterpret_cast<__half2*>(asmem + 49152 + warp * 2048 + sw1) =
                __floats2half2_rn(y1.x, y1.y);
            *reinterpret_cast<__half2*>(asmem + 49152 + warp * 2048 + sw2) =
                __floats2half2_rn(y2.x, y2.y);
        }
        __syncwarp();

        uint32_t aQ[4][4];
        #pragma unroll
        for (int ks = 0; ks < 4; ks++)
            ldsm4(aQ[ks], Qs + (uint32_t)(rA * 128) +
                          ((uint32_t)(((2 * ks + cq) ^ r7)) << 4));

        float m0 = snk, m1 = snk, l0 = 0.f, l1 = 0.f;
        float ofr[8][4];
        #pragma unroll
        for (int dn = 0; dn < 8; dn++)
            #pragma unroll
            for (int c = 0; c < 4; c++) ofr[dn][c] = 0.f;

        const int b_lo = (mt >= 2) ? 1 : 0;
        for (int bb = 0; bb < 5; bb++) {
            const int b = b_lo + bb;

            float sf[4][4];
            #pragma unroll
            for (int nt = 0; nt < 4; nt++)
                #pragma unroll
                for (int c = 0; c < 4; c++) sf[nt][c] = 0.f;

            #pragma unroll
            for (int ks = 0; ks < 4; ks++) {
                uint32_t bk0[4], bk1[4];
                const uint32_t chsw = (uint32_t)(((2 * ks + cq) ^ r7)) << 4;
                ldsm4(bk0, Ks + (uint32_t)((32 * b + rA) * 128) + chsw);
                ldsm4(bk1, Ks + (uint32_t)((32 * b + 16 + rA) * 128) + chsw);
                mma16816(sf[0], aQ[ks], bk0[0], bk0[2]);
                mma16816(sf[1], aQ[ks], bk0[1], bk0[3]);
                mma16816(sf[2], aQ[ks], bk1[0], bk1[2]);
                mma16816(sf[3], aQ[ks], bk1[1], bk1[3]);
            }

            const int jb  = i0 - 128 + 32 * b;
            const int ir0 = i_base + (lane >> 2);
            const int ir1 = ir0 + 8;
            float bm0 = -1e30f, bm1 = -1e30f;
            #pragma unroll
            for (int nt = 0; nt < 4; nt++) {
                const int jc = jb + nt * 8 + 2 * (lane & 3);
                #pragma unroll
                for (int c = 0; c < 2; c++) {
                    const int j = jc + c;
                    const float s0 = sf[nt][c] * ATT_SCALE;
                    const float s1 = sf[nt][c + 2] * ATT_SCALE;
                    const bool ok0 = (j >= 0) && (j <= ir0) && (ir0 - j < 128);
                    const bool ok1 = (j >= 0) && (j <= ir1) && (ir1 - j < 128);
                    sf[nt][c]     = ok0 ? s0 : -1e30f;
                    sf[nt][c + 2] = ok1 ? s1 : -1e30f;
                    bm0 = fmaxf(bm0, sf[nt][c]);
                    bm1 = fmaxf(bm1, sf[nt][c + 2]);
                }
            }
            bm0 = fmaxf(bm0, __shfl_xor_sync(0xFFFFFFFFu, bm0, 1));
            bm0 = fmaxf(bm0, __shfl_xor_sync(0xFFFFFFFFu, bm0, 2));
            bm1 = fmaxf(bm1, __shfl_xor_sync(0xFFFFFFFFu, bm1, 1));
            bm1 = fmaxf(bm1, __shfl_xor_sync(0xFFFFFFFFu, bm1, 2));

            const float nm0 = fmaxf(m0, bm0), nm1 = fmaxf(m1, bm1);
            const float sc0 = __expf(m0 - nm0), sc1 = __expf(m1 - nm1);
            m0 = nm0; m1 = nm1;
            l0 *= sc0; l1 *= sc1;
            #pragma unroll
            for (int dn = 0; dn < 8; dn++) {
                ofr[dn][0] *= sc0; ofr[dn][1] *= sc0;
                ofr[dn][2] *= sc1; ofr[dn][3] *= sc1;
            }

            uint32_t P01[4], P23[4];
            #pragma unroll
            for (int nt = 0; nt < 4; nt++) {
                const float p0 = __expf(sf[nt][0] - m0);
                const float p1 = __expf(sf[nt][1] - m0);
                const float p2 = __expf(sf[nt][2] - m1);
                const float p3 = __expf(sf[nt][3] - m1);
                l0 += p0 + p1;  l1 += p2 + p3;
                const __half2 h01 = __floats2half2_rn(p0, p1);
                const __half2 h23 = __floats2half2_rn(p2, p3);
                P01[nt] = *reinterpret_cast<const uint32_t*>(&h01);
                P23[nt] = *reinterpret_cast<const uint32_t*>(&h23);
            }

            #pragma unroll
            for (int kt = 0; kt < 2; kt++) {
                uint32_t aP[4] = {P01[2 * kt], P23[2 * kt],
                                  P01[2 * kt + 1], P23[2 * kt + 1]};
                const int vr = 32 * b + 16 * kt + vrow_l;
                #pragma unroll
                for (int dp = 0; dp < 4; dp++) {
                    uint32_t bv[4];
                    ldsm4t(bv, Vs + (uint32_t)(vr * 128) +
                               ((uint32_t)(((2 * dp + vnsel) ^ (vr & 7))) << 4));
                    mma16816(ofr[2 * dp],     aP, bv[0], bv[2]);
                    mma16816(ofr[2 * dp + 1], aP, bv[1], bv[3]);
                }
            }
        }

        l0 += __shfl_xor_sync(0xFFFFFFFFu, l0, 1);
        l0 += __shfl_xor_sync(0xFFFFFFFFu, l0, 2);
        l1 += __shfl_xor_sync(0xFFFFFFFFu, l1, 1);
        l1 += __shfl_xor_sync(0xFFFFFFFFu, l1, 2);
        l0 += __expf(snk - m0);
        l1 += __expf(snk - m1);
        const float inv0 = 1.f / l0, inv1 = 1.f / l1;

        const int r0 = i_base + (lane >> 2);
        #pragma unroll
        for (int dn = 0; dn < 8; dn++) {
            const int col = h * 64 + dn * 8 + 2 * (lane & 3);
            const __half2 o0 = __floats2half2_rn(ofr[dn][0] * inv0, ofr[dn][1] * inv0);
            const __half2 o1 = __floats2half2_rn(ofr[dn][2] * inv1, ofr[dn][3] * inv1);
            *reinterpret_cast<__half2*>(out_hi + (size_t)r0 * Q_SIZE + col)       = o0;
            *reinterpret_cast<__half2*>(out_hi + (size_t)(r0 + 8) * Q_SIZE + col) = o1;
        }
    }
}

// ---------------------------------------------------------------------------
// Launch — serial chain, default stream.
// ---------------------------------------------------------------------------
extern "C" void kernel_launch(void* const* d_in, const int* in_sizes, int n_in,
                              void* d_out, int out_size)
{
    const int*   positions = (const int*)  d_in[0];
    const float* hidden    = (const float*)d_in[1];
    const float* W_qkv     = (const float*)d_in[2];
    const float* b_qkv     = (const float*)d_in[3];
    const float* W_o       = (const float*)d_in[4];
    const float* b_o       = (const float*)d_in[5];
    const float* sinks     = (const float*)d_in[6];
    float* out = (float*)d_out;

    float *qkv, *rc, *rs;
    __half *h_hi, *wq_hi, *wo_hi, *a_hi;
    cudaGetSymbolAddress((void**)&qkv,   g_qkv);
    cudaGetSymbolAddress((void**)&h_hi,  g_h_hi);
    cudaGetSymbolAddress((void**)&wq_hi, g_wq_hi);
    cudaGetSymbolAddress((void**)&wo_hi, g_wo_hi);
    cudaGetSymbolAddress((void**)&a_hi,  g_a_hi);
    cudaGetSymbolAddress((void**)&rc,    g_rcos);
    cudaGetSymbolAddress((void**)&rs,    g_rsin);

    static bool attr_done = false;
    if (!attr_done) {
        cudaFuncSetAttribute(hgemm1_kernel,
                             cudaFuncAttributeMaxDynamicSharedMemorySize, GEMM_DSMEM);
        cudaFuncSetAttribute(attn_mma_kernel,
                             cudaFuncAttributeMaxDynamicSharedMemorySize, ATTN_DSMEM);
        attr_done = true;
    }

    // 0) fused preprocessing (splits, transposes, rope table)
    preproc_kernel<<<PP_TOTAL_BLOCKS, 256>>>(hidden, W_qkv, W_o, positions,
                                             h_hi, wq_hi, wo_hi, rc, rs);
    // 1) QKV projection
    {
        dim3 grid(QKV_COLS / 128, T_LEN / 128);
        hgemm1_kernel<<<grid, 256, GEMM_DSMEM>>>(h_hi, wq_hi,
                                                 b_qkv, qkv, QKV_COLS, HIDDEN);
    }
    // 2) tensor-core flash attention (rope fused into staging)
    {
        dim3 grid(T_LEN / 64, N_KV);
        attn_mma_kernel<<<grid, 256, ATTN_DSMEM>>>(qkv, sinks, rc, rs, a_hi);
    }
    // 3) O projection
    {
        dim3 grid(O_NPAD / 128, T_LEN / 128);
        hgemm1_kernel<<<grid, 256, GEMM_DSMEM>>>(a_hi, wo_hi,
                                                 b_o, out, HIDDEN, Q_SIZE);
    }
}

// round 12
// speedup vs baseline: 2.2281x; 1.0475x over previous
#include <cuda_runtime.h>
#include <cuda_fp16.h>
#include <cstdint>
#include <cmath>

// ---------------------------------------------------------------------------
// GPT-OSS attention block on sm_100 (legacy mma.sync path).
// Round 12: vectorized (float4/uint4) weight conversion; QKV GEMM emits V
// columns directly as fp16 (bit-identical); attention stages V via cp.async
// overlapping the K-RoPE staging. GEMM core + attention core unchanged.
// ---------------------------------------------------------------------------

#define T_LEN      1536
#define HIDDEN     2880
#define N_HEADS    64
#define N_KV       8
#define HEAD_DIM   64
#define WINDOW     128
#define Q_SIZE     4096
#define KV_SIZE    512
#define QKV_COLS   5120
#define O_NPAD     2944
#define ATT_SCALE  0.125f

// ---------------- scratch ---------------------------------------------------
__device__ __align__(256) float  g_qkv  [(size_t)T_LEN * QKV_COLS];   // Q+K fp32 (V region unused)
__device__ __align__(256) __half g_v16  [(size_t)T_LEN * KV_SIZE];    // V fp16
__device__ __align__(256) __half g_h_hi [(size_t)T_LEN * HIDDEN];
__device__ __align__(256) __half g_wq_hi[(size_t)QKV_COLS * HIDDEN];  // [N,K]
__device__ __align__(256) __half g_wo_hi[(size_t)O_NPAD * Q_SIZE];    // [N,K]
__device__ __align__(256) __half g_a_hi [(size_t)T_LEN * Q_SIZE];
__device__ __align__(256) float  g_rcos [(size_t)T_LEN * 32];
__device__ __align__(256) float  g_rsin [(size_t)T_LEN * 32];

// ---------------- helpers ---------------------------------------------------
static __device__ __forceinline__ uint32_t smem_u32(const void* p) {
    uint32_t a;
    asm("{ .reg .u64 t; cvta.to.shared.u64 t, %1; cvt.u32.u64 %0, t; }"
        : "=r"(a) : "l"(p));
    return a;
}

#define CP_ASYNC16(dst, src) \
    asm volatile("cp.async.cg.shared.global [%0], [%1], 16;" :: "r"(dst), "l"(src))
#define CP_COMMIT() asm volatile("cp.async.commit_group;")
#define CP_WAIT1()  asm volatile("cp.async.wait_group 1;")
#define CP_WAIT0()  asm volatile("cp.async.wait_group 0;")

static __device__ __forceinline__ void ldsm4(uint32_t* r, uint32_t addr) {
    asm volatile("ldmatrix.sync.aligned.m8n8.x4.shared.b16 {%0,%1,%2,%3}, [%4];"
                 : "=r"(r[0]), "=r"(r[1]), "=r"(r[2]), "=r"(r[3]) : "r"(addr));
}

static __device__ __forceinline__ void ldsm4t(uint32_t* r, uint32_t addr) {
    asm volatile("ldmatrix.sync.aligned.m8n8.x4.trans.shared.b16 {%0,%1,%2,%3}, [%4];"
                 : "=r"(r[0]), "=r"(r[1]), "=r"(r[2]), "=r"(r[3]) : "r"(addr));
}

static __device__ __forceinline__ void mma16816(float* d, const uint32_t* a,
                                                uint32_t b0, uint32_t b1) {
    asm volatile("mma.sync.aligned.m16n8k16.row.col.f32.f16.f16.f32 "
                 "{%0,%1,%2,%3}, {%4,%5,%6,%7}, {%8,%9}, {%0,%1,%2,%3};"
                 : "+f"(d[0]), "+f"(d[1]), "+f"(d[2]), "+f"(d[3])
                 : "r"(a[0]), "r"(a[1]), "r"(a[2]), "r"(a[3]), "r"(b0), "r"(b1));
}

// ---------------------------------------------------------------------------
// 1-pass fp16 HMMA GEMM (core unchanged). If v16 != nullptr, tiles fully in
// the V-column range [4608, 5120) store fp16 to v16 instead of fp32 to C.
// ---------------------------------------------------------------------------
#define GS           3
#define TILE_BYTES   16384
#define STAGE_BYTES  (2 * TILE_BYTES)
#define GEMM_DSMEM   (GS * STAGE_BYTES + 1024)
#define V_COL0       4608

static __device__ __forceinline__ void load_chunk(
    uint32_t st,
    const __half* __restrict__ Ah, const __half* __restrict__ Bh,
    int m0, int n0, int kk, int K, int tid)
{
    #pragma unroll
    for (int i = 0; i < 4; i++) {
        int ch  = tid + (i << 8);
        int rw  = ch >> 3;
        int c16 = ch & 7;
        uint32_t off = (uint32_t)(rw << 7) + (uint32_t)(c16 << 4);
        uint32_t sw  = off ^ ((off >> 3) & 0x70);
        const char* sa = (const char*)(Ah + (size_t)(m0 + rw) * K + kk) + (c16 << 4);
        const char* sb = (const char*)(Bh + (size_t)(n0 + rw) * K + kk) + (c16 << 4);
        CP_ASYNC16(st + sw,              sa);
        CP_ASYNC16(st + TILE_BYTES + sw, sb);
    }
}

__global__ __launch_bounds__(256, 2)
void hgemm1_kernel(const __half* __restrict__ A_hi,
                   const __half* __restrict__ B_hi,
                   const float* __restrict__ bias, float* __restrict__ C,
                   __half* __restrict__ v16,
                   int Nreal, int K)
{
    extern __shared__ char dynsmem[];
    const uint32_t tile0 = (smem_u32(dynsmem) + 1023u) & ~1023u;

    const int tid  = threadIdx.x;
    const int wid  = tid >> 5;
    const int lane = tid & 31;
    const int m0   = blockIdx.y * 128;
    const int n0   = blockIdx.x * 128;
    const int wm   = (wid & 1) * 64;
    const int wn   = (wid >> 1) * 32;

    const int r7 = lane & 7;
    const int q  = lane >> 3;
    const int rA = ((q & 1) << 3) + r7;
    const int cq = q >> 1;

    const int nch = K >> 6;

    float acc[4][4][4];
    #pragma unroll
    for (int a = 0; a < 4; a++)
        #pragma unroll
        for (int b = 0; b < 4; b++)
            #pragma unroll
            for (int c = 0; c < 4; c++) acc[a][b][c] = 0.0f;

    #pragma unroll
    for (int c = 0; c < GS - 1; c++) {
        load_chunk(tile0 + c * STAGE_BYTES, A_hi, B_hi, m0, n0, c << 6, K, tid);
        CP_COMMIT();
    }

    int stage_c = 0, stage_p = GS - 1;
    for (int c = 0; c < nch; c++) {
        CP_WAIT1();
        __syncthreads();

        if (c + GS - 1 < nch)
            load_chunk(tile0 + stage_p * STAGE_BYTES, A_hi, B_hi,
                       m0, n0, (c + GS - 1) << 6, K, tid);
        CP_COMMIT();
        if (++stage_p == GS) stage_p = 0;

        const uint32_t aB = tile0 + stage_c * STAGE_BYTES;
        const uint32_t bB = aB + TILE_BYTES;
        if (++stage_c == GS) stage_c = 0;

        #pragma unroll
        for (int ks = 0; ks < 4; ks++) {
            uint32_t afr[4][4], bfr[2][4];
            const uint32_t chsw = (uint32_t)(((ks * 2 + cq) ^ r7) << 4);
            #pragma unroll
            for (int mt = 0; mt < 4; mt++)
                ldsm4(afr[mt], aB + (uint32_t)((wm + mt * 16 + rA) << 7) + chsw);
            #pragma unroll
            for (int ng = 0; ng < 2; ng++)
                ldsm4(bfr[ng], bB + (uint32_t)((wn + ng * 16 + rA) << 7) + chsw);

            #pragma unroll
            for (int mt = 0; mt < 4; mt++)
                #pragma unroll
                for (int nt = 0; nt < 4; nt++) {
                    const int ng = nt >> 1, hl = nt & 1;
                    mma16816(acc[mt][nt], afr[mt], bfr[ng][hl], bfr[ng][hl + 2]);
                }
        }
    }

    const int trow = lane >> 2;
    const int tcol = (lane & 3) * 2;
    const bool vtile = (v16 != nullptr) && (n0 >= V_COL0);
    #pragma unroll
    for (int mt = 0; mt < 4; mt++) {
        #pragma unroll
        for (int nt = 0; nt < 4; nt++) {
            const int col = n0 + wn + nt * 8 + tcol;
            if (col < Nreal) {
                const float2 b2 = *reinterpret_cast<const float2*>(bias + col);
                const int row0 = m0 + wm + mt * 16 + trow;
                float2 o0, o1;
                o0.x = acc[mt][nt][0] + b2.x;  o0.y = acc[mt][nt][1] + b2.y;
                o1.x = acc[mt][nt][2] + b2.x;  o1.y = acc[mt][nt][3] + b2.y;
                if (vtile) {
                    const int vc = col - V_COL0;
                    *reinterpret_cast<__half2*>(v16 + (size_t)row0 * KV_SIZE + vc) =
                        __floats2half2_rn(o0.x, o0.y);
                    *reinterpret_cast<__half2*>(v16 + (size_t)(row0 + 8) * KV_SIZE + vc) =
                        __floats2half2_rn(o1.x, o1.y);
                } else {
                    *reinterpret_cast<float2*>(C + (size_t)row0 * Nreal + col)       = o0;
                    *reinterpret_cast<float2*>(C + (size_t)(row0 + 8) * Nreal + col) = o1;
                }
            }
        }
    }
}

// ---------------------------------------------------------------------------
// Fused preprocessing, vectorized.
//   job0: hidden fp32 -> fp16                       (4320 blocks)
//   job1: W_qkv [2880,5120] -> wq_hi [5120,2880]    (7200 blocks, 64k x 32n)
//   job2: W_o   [4096,2880] -> wo_hi [2944,4096]    (5888 blocks, 64k x 32n)
//   job3: RoPE cos/sin table                        (192 blocks)
// ---------------------------------------------------------------------------
#define PP_SPLIT_BLOCKS  4320
#define PP_THI1_BLOCKS   7200    // (5120/32) x (2880/64)
#define PP_THI2_BLOCKS   5888    // (2944/32) x (4096/64)
#define PP_ROPE_BLOCKS   192
#define PP_TOTAL_BLOCKS  (PP_SPLIT_BLOCKS + PP_THI1_BLOCKS + PP_THI2_BLOCKS + PP_ROPE_BLOCKS)

__global__ __launch_bounds__(256)
void preproc_kernel(const float* __restrict__ hidden,
                    const float* __restrict__ W_qkv,
                    const float* __restrict__ W_o,
                    const int* __restrict__ positions,
                    __half* __restrict__ h_hi,
                    __half* __restrict__ wq_hi,
                    __half* __restrict__ wo_hi,
                    float* __restrict__ rcos,
                    float* __restrict__ rsin)
{
    __shared__ float tile[64][33];
    const int bid = blockIdx.x;
    const int tid = threadIdx.x;

    if (bid < PP_SPLIT_BLOCKS) {
        const int i = bid * 256 + tid;
        float4 v = reinterpret_cast<const float4*>(hidden)[i];
        reinterpret_cast<__half2*>(h_hi)[2 * i + 0] =
            __halves2half2(__float2half_rn(v.x), __float2half_rn(v.y));
        reinterpret_cast<__half2*>(h_hi)[2 * i + 1] =
            __halves2half2(__float2half_rn(v.z), __float2half_rn(v.w));
        return;
    }

    if (bid < PP_SPLIT_BLOCKS + PP_THI1_BLOCKS + PP_THI2_BLOCKS) {
        const bool j1 = bid < PP_SPLIT_BLOCKS + PP_THI1_BLOCKS;
        const int  b  = j1 ? (bid - PP_SPLIT_BLOCKS)
                           : (bid - PP_SPLIT_BLOCKS - PP_THI1_BLOCKS);
        const int  nx = j1 ? (QKV_COLS / 32) : (O_NPAD / 32);
        const int  K  = j1 ? HIDDEN : Q_SIZE;
        const int  N  = j1 ? QKV_COLS : HIDDEN;
        const float* __restrict__ W = j1 ? W_qkv : W_o;
        __half* __restrict__ dst    = j1 ? wq_hi : wo_hi;

        const int n0 = (b % nx) * 32;
        const int k0 = (b / nx) * 64;

        // load 64 rows x 32 cols via float4 (2 per thread)
        #pragma unroll
        for (int i = 0; i < 2; i++) {
            const int id = tid + (i << 8);      // 0..511
            const int kr = id >> 3;             // 0..63
            const int c4 = (id & 7) * 4;        // 0..28
            const int n  = n0 + c4;
            float4 v = make_float4(0.f, 0.f, 0.f, 0.f);
            if (n < N)
                v = *reinterpret_cast<const float4*>(W + (size_t)(k0 + kr) * N + n);
            tile[kr][c4 + 0] = v.x;  tile[kr][c4 + 1] = v.y;
            tile[kr][c4 + 2] = v.z;  tile[kr][c4 + 3] = v.w;
        }
        __syncthreads();

        // write 32 n-rows x 64 k (8 halves = uint4 per thread)
        const int nr = tid >> 3;                // 0..31
        const int kc = (tid & 7) * 8;           // 0..56
        __half hb[8];
        #pragma unroll
        for (int x = 0; x < 8; x++)
            hb[x] = __float2half_rn(tile[kc + x][nr]);
        *reinterpret_cast<uint4*>(dst + (size_t)(n0 + nr) * K + k0 + kc) =
            *reinterpret_cast<const uint4*>(hb);
        return;
    }

    // job3: RoPE table
    {
        const int i = (bid - PP_SPLIT_BLOCKS - PP_THI1_BLOCKS - PP_THI2_BLOCKS) * 256 + tid;
        if (i >= T_LEN * 32) return;
        const int d = i & 31;
        const int t = i >> 5;

        const float p = (float)positions[t];
        const float lnB   = logf(150000.0f);
        const float freq  = expf(lnB * ((float)d / 32.0f));
        const float conc  = 0.1f * logf(32.0f) + 1.0f;
        const float twoPi = 6.283185307179586f;
        const float low   = 32.0f * logf(4096.0f / (32.0f * twoPi)) / lnB;
        const float high  = 32.0f * logf(4096.0f / (1.0f  * twoPi)) / lnB;
        float ramp = ((float)d - low) / (high - low);
        ramp = fminf(fmaxf(ramp, 0.0f), 1.0f);
        const float inv_freq = ramp / (32.0f * freq) + (1.0f - ramp) / freq;

        const float ang = p * inv_freq;
        rcos[i] = cosf(ang) * conc;
        rsin[i] = sinf(ang) * conc;
    }
}

// ---------------------------------------------------------------------------
// Tensor-core flash attention with sink; RoPE from table during K/Q staging;
// V staged via cp.async from the fp16 V buffer (overlaps K staging).
// ---------------------------------------------------------------------------
#define AROWS       192
#define ATTN_DSMEM  65536

__global__ __launch_bounds__(256, 2)
void attn_mma_kernel(const float* __restrict__ qkv,
                     const __half* __restrict__ v16,
                     const float* __restrict__ sinks,
                     const float* __restrict__ rcos,
                     const float* __restrict__ rsin,
                     __half* __restrict__ out_hi)
{
    extern __shared__ char asmem[];
    const uint32_t sbase = smem_u32(asmem);
    const uint32_t Ks = sbase;
    const uint32_t Vs = sbase + 24576;

    const int tid  = threadIdx.x;
    const int warp = tid >> 5;
    const int lane = tid & 31;
    const int i0   = blockIdx.x * 64;
    const int kv   = blockIdx.y;
    const int h    = kv * 8 + warp;
    const uint32_t Qs = sbase + 49152 + warp * 2048;

    // ---- V staging: cp.async 16B chunks (fp16 source, rows are 128B) ----
    for (int idx = tid; idx < AROWS * 8; idx += 256) {
        const int r = idx >> 3, c16 = idx & 7;
        const int j = i0 - 128 + r;
        const uint32_t off = (uint32_t)(r * 128) + ((uint32_t)(c16 ^ (r & 7)) << 4);
        if (j >= 0) {
            CP_ASYNC16(Vs + off,
                       (const char*)(v16 + (size_t)j * KV_SIZE + kv * 64) + (c16 << 4));
        } else {
            *reinterpret_cast<uint4*>(asmem + 24576 + off) = make_uint4(0u, 0u, 0u, 0u);
        }
    }
    CP_COMMIT();

    // ---- K staging with RoPE (pairs d, d+32), fp16 swizzled ----
    for (int idx = tid; idx < AROWS * 16; idx += 256) {
        const int r = idx >> 4, d2 = idx & 15;
        const int j = i0 - 128 + r;
        float2 y1 = make_float2(0.f, 0.f), y2 = make_float2(0.f, 0.f);
        if (j >= 0) {
            const float* src = qkv + (size_t)j * QKV_COLS + Q_SIZE + kv * 64;
            const float2 x1 = *reinterpret_cast<const float2*>(src + 2 * d2);
            const float2 x2 = *reinterpret_cast<const float2*>(src + 2 * d2 + 32);
            const float2 cc = *reinterpret_cast<const float2*>(rcos + j * 32 + 2 * d2);
            const float2 ss = *reinterpret_cast<const float2*>(rsin + j * 32 + 2 * d2);
            y1.x = x1.x * cc.x - x2.x * ss.x;  y1.y = x1.y * cc.y - x2.y * ss.y;
            y2.x = x2.x * cc.x + x1.x * ss.x;  y2.y = x2.y * cc.y + x1.y * ss.y;
        }
        const int d2b = d2 + 16;
        const uint32_t sw1 = (uint32_t)(r * 128) +
                             ((uint32_t)((d2 >> 2) ^ (r & 7)) << 4) + (d2 & 3) * 4;
        const uint32_t sw2 = (uint32_t)(r * 128) +
                             ((uint32_t)((d2b >> 2) ^ (r & 7)) << 4) + (d2b & 3) * 4;
        *reinterpret_cast<__half2*>(asmem + sw1) = __floats2half2_rn(y1.x, y1.y);
        *reinterpret_cast<__half2*>(asmem + sw2) = __floats2half2_rn(y2.x, y2.y);
    }
    CP_WAIT0();
    __syncthreads();

    const float snk = sinks[h];
    const int r7 = lane & 7;
    const int qq = lane >> 3;
    const int rA = ((qq & 1) << 3) + r7;
    const int cq = qq >> 1;
    const int vrow_l = (lane & 7) + ((lane >> 4) << 3);
    const int vnsel  = (lane >> 3) & 1;

    for (int mt = 0; mt < 4; mt++) {
        const int i_base = i0 + mt * 16;

        __syncwarp();
        for (int e = lane; e < 256; e += 32) {
            const int r = e >> 4, d2 = e & 15;
            const int t = i_base + r;
            const float* src = qkv + (size_t)t * QKV_COLS + h * 64;
            const float2 x1 = *reinterpret_cast<const float2*>(src + 2 * d2);
            const float2 x2 = *reinterpret_cast<const float2*>(src + 2 * d2 + 32);
            const float2 cc = *reinterpret_cast<const float2*>(rcos + t * 32 + 2 * d2);
            const float2 ss = *reinterpret_cast<const float2*>(rsin + t * 32 + 2 * d2);
            float2 y1, y2;
            y1.x = x1.x * cc.x - x2.x * ss.x;  y1.y = x1.y * cc.y - x2.y * ss.y;
            y2.x = x2.x * cc.x + x1.x * ss.x;  y2.y = x2.y * cc.y + x1.y * ss.y;
            const int d2b = d2 + 16;
            const uint32_t sw1 = (uint32_t)(r * 128) +
                                 ((uint32_t)((d2 >> 2) ^ (r & 7)) << 4) + (d2 & 3) * 4;
            const uint32_t sw2 = (uint32_t)(r * 128) +
                                 ((uint32_t)((d2b >> 2) ^ (r & 7)) << 4) + (d2b & 3) * 4;
            *reinterpret_cast<__half2*>(asmem + 49152 + warp * 2048 + sw1) =
                __floats2half2_rn(y1.x, y1.y);
            *reinterpret_cast<__half2*>(asmem + 49152 + warp * 2048 + sw2) =
                __floats2half2_rn(y2.x, y2.y);
        }
        __syncwarp();

        uint32_t aQ[4][4];
        #pragma unroll
        for (int ks = 0; ks < 4; ks++)
            ldsm4(aQ[ks], Qs + (uint32_t)(rA * 128) +
                          ((uint32_t)(((2 * ks + cq) ^ r7)) << 4));

        float m0 = snk, m1 = snk, l0 = 0.f, l1 = 0.f;
        float ofr[8][4];
        #pragma unroll
        for (int dn = 0; dn < 8; dn++)
            #pragma unroll
            for (int c = 0; c < 4; c++) ofr[dn][c] = 0.f;

        const int b_lo = (mt >= 2) ? 1 : 0;
        for (int bb = 0; bb < 5; bb++) {
            const int b = b_lo + bb;

            float sf[4][4];
            #pragma unroll
            for (int nt = 0; nt < 4; nt++)
                #pragma unroll
                for (int c = 0; c < 4; c++) sf[nt][c] = 0.f;

            #pragma unroll
            for (int ks = 0; ks < 4; ks++) {
                uint32_t bk0[4], bk1[4];
                const uint32_t chsw = (uint32_t)(((2 * ks + cq) ^ r7)) << 4;
                ldsm4(bk0, Ks + (uint32_t)((32 * b + rA) * 128) + chsw);
                ldsm4(bk1, Ks + (uint32_t)((32 * b + 16 + rA) * 128) + chsw);
                mma16816(sf[0], aQ[ks], bk0[0], bk0[2]);
                mma16816(sf[1], aQ[ks], bk0[1], bk0[3]);
                mma16816(sf[2], aQ[ks], bk1[0], bk1[2]);
                mma16816(sf[3], aQ[ks], bk1[1], bk1[3]);
            }

            const int jb  = i0 - 128 + 32 * b;
            const int ir0 = i_base + (lane >> 2);
            const int ir1 = ir0 + 8;
            float bm0 = -1e30f, bm1 = -1e30f;
            #pragma unroll
            for (int nt = 0; nt < 4; nt++) {
                const int jc = jb + nt * 8 + 2 * (lane & 3);
                #pragma unroll
                for (int c = 0; c < 2; c++) {
                    const int j = jc + c;
                    const float s0 = sf[nt][c] * ATT_SCALE;
                    const float s1 = sf[nt][c + 2] * ATT_SCALE;
                    const bool ok0 = (j >= 0) && (j <= ir0) && (ir0 - j < 128);
                    const bool ok1 = (j >= 0) && (j <= ir1) && (ir1 - j < 128);
                    sf[nt][c]     = ok0 ? s0 : -1e30f;
                    sf[nt][c + 2] = ok1 ? s1 : -1e30f;
                    bm0 = fmaxf(bm0, sf[nt][c]);
                    bm1 = fmaxf(bm1, sf[nt][c + 2]);
                }
            }
            bm0 = fmaxf(bm0, __shfl_xor_sync(0xFFFFFFFFu, bm0, 1));
            bm0 = fmaxf(bm0, __shfl_xor_sync(0xFFFFFFFFu, bm0, 2));
            bm1 = fmaxf(bm1, __shfl_xor_sync(0xFFFFFFFFu, bm1, 1));
            bm1 = fmaxf(bm1, __shfl_xor_sync(0xFFFFFFFFu, bm1, 2));

            const float nm0 = fmaxf(m0, bm0), nm1 = fmaxf(m1, bm1);
            const float sc0 = __expf(m0 - nm0), sc1 = __expf(m1 - nm1);
            m0 = nm0; m1 = nm1;
            l0 *= sc0; l1 *= sc1;
            #pragma unroll
            for (int dn = 0; dn < 8; dn++) {
                ofr[dn][0] *= sc0; ofr[dn][1] *= sc0;
                ofr[dn][2] *= sc1; ofr[dn][3] *= sc1;
            }

            uint32_t P01[4], P23[4];
            #pragma unroll
            for (int nt = 0; nt < 4; nt++) {
                const float p0 = __expf(sf[nt][0] - m0);
                const float p1 = __expf(sf[nt][1] - m0);
                const float p2 = __expf(sf[nt][2] - m1);
                const float p3 = __expf(sf[nt][3] - m1);
                l0 += p0 + p1;  l1 += p2 + p3;
                const __half2 h01 = __floats2half2_rn(p0, p1);
                const __half2 h23 = __floats2half2_rn(p2, p3);
                P01[nt] = *reinterpret_cast<const uint32_t*>(&h01);
                P23[nt] = *reinterpret_cast<const uint32_t*>(&h23);
            }

            #pragma unroll
            for (int kt = 0; kt < 2; kt++) {
                uint32_t aP[4] = {P01[2 * kt], P23[2 * kt],
                                  P01[2 * kt + 1], P23[2 * kt + 1]};
                const int vr = 32 * b + 16 * kt + vrow_l;
                #pragma unroll
                for (int dp = 0; dp < 4; dp++) {
                    uint32_t bv[4];
                    ldsm4t(bv, Vs + (uint32_t)(vr * 128) +
                               ((uint32_t)(((2 * dp + vnsel) ^ (vr & 7))) << 4));
                    mma16816(ofr[2 * dp],     aP, bv[0], bv[2]);
                    mma16816(ofr[2 * dp + 1], aP, bv[1], bv[3]);
                }
            }
        }

        l0 += __shfl_xor_sync(0xFFFFFFFFu, l0, 1);
        l0 += __shfl_xor_sync(0xFFFFFFFFu, l0, 2);
        l1 += __shfl_xor_sync(0xFFFFFFFFu, l1, 1);
        l1 += __shfl_xor_sync(0xFFFFFFFFu, l1, 2);
        l0 += __expf(snk - m0);
        l1 += __expf(snk - m1);
        const float inv0 = 1.f / l0, inv1 = 1.f / l1;

        const int r0 = i_base + (lane >> 2);
        #pragma unroll
        for (int dn = 0; dn < 8; dn++) {
            const int col = h * 64 + dn * 8 + 2 * (lane & 3);
            const __half2 o0 = __floats2half2_rn(ofr[dn][0] * inv0, ofr[dn][1] * inv0);
            const __half2 o1 = __floats2half2_rn(ofr[dn][2] * inv1, ofr[dn][3] * inv1);
            *reinterpret_cast<__half2*>(out_hi + (size_t)r0 * Q_SIZE + col)       = o0;
            *reinterpret_cast<__half2*>(out_hi + (size_t)(r0 + 8) * Q_SIZE + col) = o1;
        }
    }
}

// ---------------------------------------------------------------------------
// Launch — serial chain, default stream.
// ---------------------------------------------------------------------------
extern "C" void kernel_launch(void* const* d_in, const int* in_sizes, int n_in,
                              void* d_out, int out_size)
{
    const int*   positions = (const int*)  d_in[0];
    const float* hidden    = (const float*)d_in[1];
    const float* W_qkv     = (const float*)d_in[2];
    const float* b_qkv     = (const float*)d_in[3];
    const float* W_o       = (const float*)d_in[4];
    const float* b_o       = (const float*)d_in[5];
    const float* sinks     = (const float*)d_in[6];
    float* out = (float*)d_out;

    float *qkv, *rc, *rs;
    __half *h_hi, *wq_hi, *wo_hi, *a_hi, *v16;
    cudaGetSymbolAddress((void**)&qkv,   g_qkv);
    cudaGetSymbolAddress((void**)&h_hi,  g_h_hi);
    cudaGetSymbolAddress((void**)&wq_hi, g_wq_hi);
    cudaGetSymbolAddress((void**)&wo_hi, g_wo_hi);
    cudaGetSymbolAddress((void**)&a_hi,  g_a_hi);
    cudaGetSymbolAddress((void**)&rc,    g_rcos);
    cudaGetSymbolAddress((void**)&rs,    g_rsin);
    cudaGetSymbolAddress((void**)&v16,   g_v16);

    static bool attr_done = false;
    if (!attr_done) {
        cudaFuncSetAttribute(hgemm1_kernel,
                             cudaFuncAttributeMaxDynamicSharedMemorySize, GEMM_DSMEM);
        cudaFuncSetAttribute(attn_mma_kernel,
                             cudaFuncAttributeMaxDynamicSharedMemorySize, ATTN_DSMEM);
        attr_done = true;
    }

    // 0) fused preprocessing
    preproc_kernel<<<PP_TOTAL_BLOCKS, 256>>>(hidden, W_qkv, W_o, positions,
                                             h_hi, wq_hi, wo_hi, rc, rs);
    // 1) QKV projection (V columns emitted as fp16 to v16)
    {
        dim3 grid(QKV_COLS / 128, T_LEN / 128);
        hgemm1_kernel<<<grid, 256, GEMM_DSMEM>>>(h_hi, wq_hi, b_qkv, qkv, v16,
                                                 QKV_COLS, HIDDEN);
    }
    // 2) tensor-core flash attention
    {
        dim3 grid(T_LEN / 64, N_KV);
        attn_mma_kernel<<<grid, 256, ATTN_DSMEM>>>(qkv, v16, sinks, rc, rs, a_hi);
    }
    // 3) O projection
    {
        dim3 grid(O_NPAD / 128, T_LEN / 128);
        hgemm1_kernel<<<grid, 256, GEMM_DSMEM>>>(a_hi, wo_hi, b_o, out, nullptr,
                                                 HIDDEN, Q_SIZE);
    }
}